// round 2
// baseline (speedup 1.0000x reference)
#include <cuda_runtime.h>
#include <math.h>

#define N_NODES 50000
#define E_EDGES 1600000
#define E_TOT   (E_EDGES + N_NODES)
#define HEADS   8
#define HID     128
#define IN_C    512
#define F1      (HEADS*HID)   /* 1024 */
#define OUT_C   64
#define NEG     0.2f

// ---------------- scratch (device globals: allocation-free) ----------------
__device__ float g_h1[(size_t)N_NODES * F1];      // layer1 features x@W1
__device__ float g_h2[(size_t)N_NODES * F1];      // elu(agg1 + b1)
__device__ float g_as1[N_NODES * HEADS];
__device__ float g_ad1[N_NODES * HEADS];
__device__ float g_alpha1[(size_t)E_TOT * HEADS];
__device__ float g_g2[(size_t)N_NODES * OUT_C];
__device__ float g_out2[(size_t)N_NODES * OUT_C];
__device__ float g_as2[N_NODES];
__device__ float g_ad2[N_NODES];
__device__ float g_alpha2[E_TOT];
__device__ int   g_deg[N_NODES];
__device__ int   g_rowptr[N_NODES + 1];
__device__ int   g_cursor[N_NODES];
__device__ int   g_csrsrc[E_TOT];

// ---------------- CSR build ----------------
__global__ void k_zero_deg() {
    int i = blockIdx.x * 256 + threadIdx.x;
    if (i < N_NODES) g_deg[i] = 0;
}

__global__ void k_count(const int* __restrict__ ei) {
    int e = blockIdx.x * 256 + threadIdx.x;
    if (e >= E_TOT) return;
    int dst = (e < E_EDGES) ? ei[E_EDGES + e] : (e - E_EDGES);
    atomicAdd(&g_deg[dst], 1);
}

__global__ void k_scan() {
    __shared__ int sh[1024];
    int t = threadIdx.x;
    const int chunk = (N_NODES + 1023) / 1024;
    int beg = t * chunk;
    int end = min(beg + chunk, N_NODES);
    int sum = 0;
    for (int i = beg; i < end; i++) sum += g_deg[i];
    sh[t] = sum;
    __syncthreads();
    for (int off = 1; off < 1024; off <<= 1) {
        int v = (t >= off) ? sh[t - off] : 0;
        __syncthreads();
        sh[t] += v;
        __syncthreads();
    }
    int run = sh[t] - sum;  // exclusive prefix
    for (int i = beg; i < end; i++) { g_rowptr[i] = run; run += g_deg[i]; }
    if (t == 1023) g_rowptr[N_NODES] = sh[1023];
}

__global__ void k_cursor() {
    int i = blockIdx.x * 256 + threadIdx.x;
    if (i < N_NODES) g_cursor[i] = g_rowptr[i];
}

__global__ void k_scatter(const int* __restrict__ ei) {
    int e = blockIdx.x * 256 + threadIdx.x;
    if (e >= E_TOT) return;
    int src, dst;
    if (e < E_EDGES) { src = ei[e]; dst = ei[E_EDGES + e]; }
    else             { src = e - E_EDGES; dst = src; }
    int pos = atomicAdd(&g_cursor[dst], 1);
    g_csrsrc[pos] = src;
}

// ---------------- fp32 SIMT GEMM: C[M,N] = A[M,K] @ B[K,N] ----------------
// BM=128, BN=64, BK=16, 128 threads, 8x8 per-thread tile.
__global__ void gemm_f32(const float* __restrict__ A, const float* __restrict__ B,
                         float* __restrict__ C, int M, int N, int K) {
    const int BM = 128, BN = 64, BK = 16, TM = 8, TN = 8;
    __shared__ float As[BK][BM + 4];
    __shared__ float Bs[BK][BN + 4];
    int tid = threadIdx.x;
    int brow = blockIdx.y * BM;
    int bcol = blockIdx.x * BN;
    int ar = tid >> 2;            // 0..31
    int ac = (tid & 3) * 4;       // 0,4,8,12
    int br = tid >> 4;            // 0..7
    int bc = (tid & 15) * 4;      // 0..60
    int tx = tid & 7;             // col group (8 groups * TN=8 = 64)
    int ty = tid >> 3;            // row group (16 groups * TM=8 = 128)

    float acc[TM][TN];
#pragma unroll
    for (int i = 0; i < TM; i++)
#pragma unroll
        for (int j = 0; j < TN; j++) acc[i][j] = 0.f;

    for (int k0 = 0; k0 < K; k0 += BK) {
        // load A tile (transposed into As[k][m]); guard rows past M
#pragma unroll
        for (int it = 0; it < 4; it++) {
            int row = brow + ar + it * 32;
            float4 v = make_float4(0.f, 0.f, 0.f, 0.f);
            if (row < M) v = *(const float4*)(A + (size_t)row * K + k0 + ac);
            As[ac + 0][ar + it * 32] = v.x;
            As[ac + 1][ar + it * 32] = v.y;
            As[ac + 2][ar + it * 32] = v.z;
            As[ac + 3][ar + it * 32] = v.w;
        }
        // load B tile (K mult of 16, N mult of 64 -> no guard)
#pragma unroll
        for (int it = 0; it < 2; it++) {
            float4 w = *(const float4*)(B + (size_t)(k0 + br + it * 8) * N + bcol + bc);
            *(float4*)&Bs[br + it * 8][bc] = w;
        }
        __syncthreads();
#pragma unroll
        for (int k = 0; k < BK; k++) {
            float a[TM], b[TN];
#pragma unroll
            for (int i = 0; i < TM; i++) a[i] = As[k][ty * TM + i];
#pragma unroll
            for (int j = 0; j < TN; j++) b[j] = Bs[k][tx * TN + j];
#pragma unroll
            for (int i = 0; i < TM; i++)
#pragma unroll
                for (int j = 0; j < TN; j++) acc[i][j] += a[i] * b[j];
        }
        __syncthreads();
    }
#pragma unroll
    for (int i = 0; i < TM; i++) {
        int row = brow + ty * TM + i;
        if (row >= M) continue;
#pragma unroll
        for (int j = 0; j < TN; j++) {
            C[(size_t)row * N + bcol + tx * TN + j] = acc[i][j];
        }
    }
}

// ---------------- layer-1 attention dots: as1/ad1[n,h] = h1[n,h,:].att ----------------
__global__ void k_attn1(const float* __restrict__ a_src, const float* __restrict__ a_dst) {
    int n = blockIdx.x;
    int w = threadIdx.x >> 5;     // head
    int lane = threadIdx.x & 31;
    const float* hrow = g_h1 + (size_t)n * F1 + w * HID;
    float s = 0.f, d = 0.f;
#pragma unroll
    for (int c = lane; c < HID; c += 32) {
        float hv = hrow[c];
        s += hv * a_src[w * HID + c];
        d += hv * a_dst[w * HID + c];
    }
#pragma unroll
    for (int off = 16; off > 0; off >>= 1) {
        s += __shfl_xor_sync(0xffffffffu, s, off);
        d += __shfl_xor_sync(0xffffffffu, d, off);
    }
    if (lane == 0) { g_as1[n * HEADS + w] = s; g_ad1[n * HEADS + w] = d; }
}

// ---------------- layer-1 edge softmax (one thread per (dst,head)) ----------------
__global__ void k_softmax1() {
    int idx = blockIdx.x * 256 + threadIdx.x;
    if (idx >= N_NODES * HEADS) return;
    int n = idx >> 3, h = idx & 7;
    int beg = g_rowptr[n], end = g_rowptr[n + 1];
    float adv = g_ad1[idx];
    float m = -1e30f;
    for (int p = beg; p < end; p++) {
        float l = g_as1[g_csrsrc[p] * HEADS + h] + adv;
        l = (l > 0.f) ? l : NEG * l;
        m = fmaxf(m, l);
    }
    float z = 0.f;
    for (int p = beg; p < end; p++) {
        float l = g_as1[g_csrsrc[p] * HEADS + h] + adv;
        l = (l > 0.f) ? l : NEG * l;
        float e = __expf(l - m);
        g_alpha1[(size_t)p * HEADS + h] = e;
        z += e;
    }
    float inv = 1.f / z;  // self-loop guarantees deg >= 1
    for (int p = beg; p < end; p++) g_alpha1[(size_t)p * HEADS + h] *= inv;
}

// ---------------- layer-1 aggregation + bias + ELU (block per dst node) ----------------
__global__ void k_agg1(const float* __restrict__ b1) {
    int n = blockIdx.x;
    int tid = threadIdx.x;        // 0..1023 = h*128 + c
    int h = tid >> 7;
    int beg = g_rowptr[n], end = g_rowptr[n + 1];
    float acc = 0.f;
    int p = beg;
    for (; p + 4 <= end; p += 4) {
        int s0 = g_csrsrc[p], s1 = g_csrsrc[p + 1], s2 = g_csrsrc[p + 2], s3 = g_csrsrc[p + 3];
        float a0 = g_alpha1[(size_t)(p    ) * HEADS + h];
        float a1 = g_alpha1[(size_t)(p + 1) * HEADS + h];
        float a2 = g_alpha1[(size_t)(p + 2) * HEADS + h];
        float a3 = g_alpha1[(size_t)(p + 3) * HEADS + h];
        float v0 = g_h1[(size_t)s0 * F1 + tid];
        float v1 = g_h1[(size_t)s1 * F1 + tid];
        float v2 = g_h1[(size_t)s2 * F1 + tid];
        float v3 = g_h1[(size_t)s3 * F1 + tid];
        acc += a0 * v0; acc += a1 * v1; acc += a2 * v2; acc += a3 * v3;
    }
    for (; p < end; p++) {
        acc += g_alpha1[(size_t)p * HEADS + h] * g_h1[(size_t)g_csrsrc[p] * F1 + tid];
    }
    float v = acc + b1[tid];
    g_h2[(size_t)n * F1 + tid] = (v > 0.f) ? v : (expf(v) - 1.f);   // ELU
}

// ---------------- layer-2 attention dots (warp per node) ----------------
__global__ void k_attn2(const float* __restrict__ a_src, const float* __restrict__ a_dst) {
    int n = blockIdx.x * 8 + (threadIdx.x >> 5);
    if (n >= N_NODES) return;
    int lane = threadIdx.x & 31;
    const float* grow = g_g2 + (size_t)n * OUT_C;
    float s = 0.f, d = 0.f;
#pragma unroll
    for (int c = lane; c < OUT_C; c += 32) {
        float gv = grow[c];
        s += gv * a_src[c];
        d += gv * a_dst[c];
    }
#pragma unroll
    for (int off = 16; off > 0; off >>= 1) {
        s += __shfl_xor_sync(0xffffffffu, s, off);
        d += __shfl_xor_sync(0xffffffffu, d, off);
    }
    if (lane == 0) { g_as2[n] = s; g_ad2[n] = d; }
}

// ---------------- layer-2 edge softmax (one thread per dst node) ----------------
__global__ void k_softmax2() {
    int n = blockIdx.x * 256 + threadIdx.x;
    if (n >= N_NODES) return;
    int beg = g_rowptr[n], end = g_rowptr[n + 1];
    float adv = g_ad2[n];
    float m = -1e30f;
    for (int p = beg; p < end; p++) {
        float l = g_as2[g_csrsrc[p]] + adv;
        l = (l > 0.f) ? l : NEG * l;
        m = fmaxf(m, l);
    }
    float z = 0.f;
    for (int p = beg; p < end; p++) {
        float l = g_as2[g_csrsrc[p]] + adv;
        l = (l > 0.f) ? l : NEG * l;
        float e = __expf(l - m);
        g_alpha2[p] = e;
        z += e;
    }
    float inv = 1.f / z;
    for (int p = beg; p < end; p++) g_alpha2[p] *= inv;
}

// ---------------- layer-2 aggregation (block of 64 per dst node) ----------------
__global__ void k_agg2() {
    int n = blockIdx.x;
    int tid = threadIdx.x;        // 0..63
    int beg = g_rowptr[n], end = g_rowptr[n + 1];
    float acc = 0.f;
    int p = beg;
    for (; p + 4 <= end; p += 4) {
        int s0 = g_csrsrc[p], s1 = g_csrsrc[p + 1], s2 = g_csrsrc[p + 2], s3 = g_csrsrc[p + 3];
        float a0 = g_alpha2[p], a1 = g_alpha2[p + 1], a2 = g_alpha2[p + 2], a3 = g_alpha2[p + 3];
        float v0 = g_g2[(size_t)s0 * OUT_C + tid];
        float v1 = g_g2[(size_t)s1 * OUT_C + tid];
        float v2 = g_g2[(size_t)s2 * OUT_C + tid];
        float v3 = g_g2[(size_t)s3 * OUT_C + tid];
        acc += a0 * v0; acc += a1 * v1; acc += a2 * v2; acc += a3 * v3;
    }
    for (; p < end; p++) {
        acc += g_alpha2[p] * g_g2[(size_t)g_csrsrc[p] * OUT_C + tid];
    }
    g_out2[(size_t)n * OUT_C + tid] = acc;
}

// ---------------- bias + log_softmax over 64 classes (warp per node) ----------------
__global__ void k_logsoftmax(const float* __restrict__ b2, float* __restrict__ out) {
    int n = blockIdx.x * 8 + (threadIdx.x >> 5);
    if (n >= N_NODES) return;
    int lane = threadIdx.x & 31;
    float v0 = g_out2[(size_t)n * OUT_C + lane]      + b2[lane];
    float v1 = g_out2[(size_t)n * OUT_C + 32 + lane] + b2[32 + lane];
    float m = fmaxf(v0, v1);
#pragma unroll
    for (int off = 16; off > 0; off >>= 1) m = fmaxf(m, __shfl_xor_sync(0xffffffffu, m, off));
    float s = expf(v0 - m) + expf(v1 - m);
#pragma unroll
    for (int off = 16; off > 0; off >>= 1) s += __shfl_xor_sync(0xffffffffu, s, off);
    float ls = logf(s);
    out[(size_t)n * OUT_C + lane]      = v0 - m - ls;
    out[(size_t)n * OUT_C + 32 + lane] = v1 - m - ls;
}

// ---------------- launch ----------------
extern "C" void kernel_launch(void* const* d_in, const int* in_sizes, int n_in,
                              void* d_out, int out_size) {
    const float* x     = (const float*)d_in[0];
    const int*   ei    = (const int*)  d_in[1];
    const float* W1    = (const float*)d_in[2];
    const float* asrc1 = (const float*)d_in[3];
    const float* adst1 = (const float*)d_in[4];
    const float* b1    = (const float*)d_in[5];
    const float* W2    = (const float*)d_in[6];
    const float* asrc2 = (const float*)d_in[7];
    const float* adst2 = (const float*)d_in[8];
    const float* b2    = (const float*)d_in[9];
    float* out = (float*)d_out;

    void *p_h1 = nullptr, *p_h2 = nullptr, *p_g2 = nullptr;
    cudaGetSymbolAddress(&p_h1, g_h1);
    cudaGetSymbolAddress(&p_h2, g_h2);
    cudaGetSymbolAddress(&p_g2, g_g2);

    const int TPB = 256;
    // CSR build (dst-sorted)
    k_zero_deg<<<(N_NODES + TPB - 1) / TPB, TPB>>>();
    k_count  <<<(E_TOT   + TPB - 1) / TPB, TPB>>>(ei);
    k_scan   <<<1, 1024>>>();
    k_cursor <<<(N_NODES + TPB - 1) / TPB, TPB>>>();
    k_scatter<<<(E_TOT   + TPB - 1) / TPB, TPB>>>(ei);

    // layer 1
    gemm_f32<<<dim3(F1 / 64, (N_NODES + 127) / 128), 128>>>(x, W1, (float*)p_h1,
                                                            N_NODES, F1, IN_C);
    k_attn1<<<N_NODES, 256>>>(asrc1, adst1);
    k_softmax1<<<(N_NODES * HEADS + TPB - 1) / TPB, TPB>>>();
    k_agg1<<<N_NODES, 1024>>>(b1);

    // layer 2
    gemm_f32<<<dim3(OUT_C / 64, (N_NODES + 127) / 128), 128>>>((float*)p_h2, W2,
                                                               (float*)p_g2,
                                                               N_NODES, OUT_C, F1);
    k_attn2<<<(N_NODES + 7) / 8, 256>>>(asrc2, adst2);
    k_softmax2<<<(N_NODES + TPB - 1) / TPB, TPB>>>();
    k_agg2<<<N_NODES, 64>>>();
    k_logsoftmax<<<(N_NODES + 7) / 8, 256>>>(b2, out);
}

// round 5
// speedup vs baseline: 1.3078x; 1.3078x over previous
#include <cuda_runtime.h>
#include <cuda_bf16.h>
#include <math.h>
#include <stdint.h>

#define N_NODES 50000
#define E_EDGES 1600000
#define E_TOT   (E_EDGES + N_NODES)
#define HEADS   8
#define HID     128
#define IN_C    512
#define F1      (HEADS*HID)   /* 1024 */
#define OUT_C   64
#define NEG     0.2f

// ---------------- scratch (device globals: allocation-free) ----------------
__device__ float g_h1[(size_t)N_NODES * F1];      // layer1 features x@W1 (fp32)
__device__ float g_as1[N_NODES * HEADS];
__device__ float g_ad1[N_NODES * HEADS];
__device__ float g_alpha1[(size_t)E_TOT * HEADS];
__device__ float g_g2[(size_t)N_NODES * OUT_C];
__device__ float g_out2[(size_t)N_NODES * OUT_C];
__device__ float g_as2[N_NODES];
__device__ float g_ad2[N_NODES];
__device__ float g_alpha2[E_TOT];
__device__ int   g_deg[N_NODES];
__device__ int   g_rowptr[N_NODES + 1];
__device__ int   g_cursor[N_NODES];
__device__ int   g_csrsrc[E_TOT];

// bf16 split operands for tensor-core GEMMs
__device__ __nv_bfloat16 g_xh[(size_t)N_NODES * IN_C];
__device__ __nv_bfloat16 g_xl[(size_t)N_NODES * IN_C];
__device__ __nv_bfloat16 g_h2h[(size_t)N_NODES * F1];
__device__ __nv_bfloat16 g_h2l[(size_t)N_NODES * F1];
__device__ __nv_bfloat16 g_W1th[(size_t)F1 * IN_C];   // [n][k] K-major transposed
__device__ __nv_bfloat16 g_W1tl[(size_t)F1 * IN_C];
__device__ __nv_bfloat16 g_W2th[(size_t)OUT_C * F1];
__device__ __nv_bfloat16 g_W2tl[(size_t)OUT_C * F1];

// ---------------- helpers ----------------
__device__ __forceinline__ uint32_t smem_u32(const void* p) {
    uint32_t a;
    asm("{ .reg .u64 t; cvta.to.shared.u64 t, %1; cvt.u32.u64 %0, t; }" : "=r"(a) : "l"(p));
    return a;
}
#define CP16(sa, ga) \
    asm volatile("cp.async.cg.shared.global [%0], [%1], 16;" :: "r"(sa), "l"(ga))
#define CP_COMMIT() asm volatile("cp.async.commit_group;" ::: "memory")
#define CP_WAIT1()  asm volatile("cp.async.wait_group 1;" ::: "memory")
#define CP_WAIT0()  asm volatile("cp.async.wait_group 0;" ::: "memory")

#define MMA16816(c, a, b)                                                      \
    asm volatile("mma.sync.aligned.m16n8k16.row.col.f32.bf16.bf16.f32 "        \
                 "{%0,%1,%2,%3}, {%4,%5,%6,%7}, {%8,%9}, {%0,%1,%2,%3};"       \
                 : "+f"((c)[0]), "+f"((c)[1]), "+f"((c)[2]), "+f"((c)[3])      \
                 : "r"((a)[0]), "r"((a)[1]), "r"((a)[2]), "r"((a)[3]),         \
                   "r"((b)[0]), "r"((b)[1]))

// ---------------- CSR build ----------------
__global__ void k_zero_deg() {
    int i = blockIdx.x * 256 + threadIdx.x;
    if (i < N_NODES) g_deg[i] = 0;
}
__global__ void k_count(const int* __restrict__ ei) {
    int e = blockIdx.x * 256 + threadIdx.x;
    if (e >= E_TOT) return;
    int dst = (e < E_EDGES) ? ei[E_EDGES + e] : (e - E_EDGES);
    atomicAdd(&g_deg[dst], 1);
}
__global__ void k_scan() {
    __shared__ int sh[1024];
    int t = threadIdx.x;
    const int chunk = (N_NODES + 1023) / 1024;
    int beg = t * chunk, end = min(beg + chunk, N_NODES);
    int sum = 0;
    for (int i = beg; i < end; i++) sum += g_deg[i];
    sh[t] = sum;
    __syncthreads();
    for (int off = 1; off < 1024; off <<= 1) {
        int v = (t >= off) ? sh[t - off] : 0;
        __syncthreads();
        sh[t] += v;
        __syncthreads();
    }
    int run = sh[t] - sum;
    for (int i = beg; i < end; i++) { g_rowptr[i] = run; run += g_deg[i]; }
    if (t == 1023) g_rowptr[N_NODES] = sh[1023];
}
__global__ void k_cursor() {
    int i = blockIdx.x * 256 + threadIdx.x;
    if (i < N_NODES) g_cursor[i] = g_rowptr[i];
}
__global__ void k_scatter(const int* __restrict__ ei) {
    int e = blockIdx.x * 256 + threadIdx.x;
    if (e >= E_TOT) return;
    int src, dst;
    if (e < E_EDGES) { src = ei[e]; dst = ei[E_EDGES + e]; }
    else             { src = e - E_EDGES; dst = src; }
    int pos = atomicAdd(&g_cursor[dst], 1);
    g_csrsrc[pos] = src;
}

// ---------------- bf16 hi/lo split of x ----------------
__global__ void k_split_x(const float* __restrict__ x) {
    size_t i = (size_t)blockIdx.x * 256 + threadIdx.x;
    if (i >= (size_t)N_NODES * IN_C) return;
    float v = x[i];
    __nv_bfloat16 hi = __float2bfloat16(v);
    g_xh[i] = hi;
    g_xl[i] = __float2bfloat16(v - __bfloat162float(hi));
}

// transpose + split W: W[K][N] -> Th/Tl[n][k]
__global__ void k_split_wt(const float* __restrict__ W, __nv_bfloat16* __restrict__ Th,
                           __nv_bfloat16* __restrict__ Tl, int K, int N) {
    size_t i = (size_t)blockIdx.x * 256 + threadIdx.x;
    if (i >= (size_t)K * N) return;
    int n = (int)(i / K), k = (int)(i % K);
    float v = W[(size_t)k * N + n];
    __nv_bfloat16 hi = __float2bfloat16(v);
    Th[i] = hi;
    Tl[i] = __float2bfloat16(v - __bfloat162float(hi));
}

// ---------------- warp-MMA bf16 3-pass GEMM ----------------
// C[M,Ntot] = (Ah+Al)[M,K] @ (Bh+Bl)^T  with B stored K-major [Ntot][K].
// CTA tile 128x64, BK=32, 8 warps (4x2), warp tile 32x32. Double-buffered cp.async.
// SMEM row pitch 112B (conflict-free LDS fragments, 16B-aligned cp.async).
#define GPITCH 112
#define ABYTES (128 * GPITCH)           /* 14336 */
#define BBYTES (64 * GPITCH)            /*  7168 */
#define STG    (2 * ABYTES + 2 * BBYTES) /* 43008 */
#define GSMEM  (2 * STG)                 /* 86016 */

__global__ __launch_bounds__(256, 2)
void gemm_mma(const __nv_bfloat16* __restrict__ Ah, const __nv_bfloat16* __restrict__ Al,
              const __nv_bfloat16* __restrict__ Bh, const __nv_bfloat16* __restrict__ Bl,
              float* __restrict__ C, int M, int Ntot, int K) {
    extern __shared__ __align__(16) char smraw[];
    uint32_t sbase = smem_u32(smraw);

    int tid = threadIdx.x;
    int lane = tid & 31, wid = tid >> 5;
    int wm = wid >> 1, wn = wid & 1;          // 4 x 2 warp grid
    int m0 = blockIdx.y * 128;
    int n0 = blockIdx.x * 64;
    int KT = K >> 5;                           // BK=32

    // ---- tile loader (cp.async) ----
    auto load_tile = [&](int kt, int s) {
        int k0 = kt << 5;
        uint32_t st = sbase + s * STG;
        // A hi/lo: 128 rows x 4 chunks of 16B = 512 chunks each
#pragma unroll
        for (int i = 0; i < 2; i++) {
            int c = tid + i * 256;
            int r = c >> 2, cg = c & 3;
            int gr = m0 + r; if (gr >= M) gr = M - 1;
            const char* gh = (const char*)(Ah + (size_t)gr * K + k0) + cg * 16;
            const char* gl = (const char*)(Al + (size_t)gr * K + k0) + cg * 16;
            uint32_t sa = st + r * GPITCH + cg * 16;
            CP16(sa, gh);
            CP16(sa + ABYTES, gl);
        }
        // B hi/lo: 64 rows x 4 chunks = 256 chunks each (N always mult of 64)
        {
            int r = tid >> 2, cg = tid & 3;
            const char* gh = (const char*)(Bh + (size_t)(n0 + r) * K + k0) + cg * 16;
            const char* gl = (const char*)(Bl + (size_t)(n0 + r) * K + k0) + cg * 16;
            uint32_t sa = st + 2 * ABYTES + r * GPITCH + cg * 16;
            CP16(sa, gh);
            CP16(sa + BBYTES, gl);
        }
    };

    float acc[2][4][4];
#pragma unroll
    for (int i = 0; i < 2; i++)
#pragma unroll
        for (int j = 0; j < 4; j++)
#pragma unroll
            for (int q = 0; q < 4; q++) acc[i][j][q] = 0.f;

    load_tile(0, 0);
    CP_COMMIT();

    for (int kt = 0; kt < KT; kt++) {
        int cur = kt & 1;
        if (kt + 1 < KT) { load_tile(kt + 1, cur ^ 1); CP_COMMIT(); CP_WAIT1(); }
        else             { CP_WAIT0(); }
        __syncthreads();

        const char* st = smraw + cur * STG;
#pragma unroll
        for (int ks = 0; ks < 2; ks++) {
            int kb = ks * 32;   // 16 elems * 2B
            // A fragments (hi & lo), 2 m-frags of 16 rows
            uint32_t ah[2][4], al[2][4];
#pragma unroll
            for (int mf = 0; mf < 2; mf++) {
                const char* pa = st + (wm * 32 + mf * 16 + (lane >> 2)) * GPITCH
                               + kb + (lane & 3) * 4;
                ah[mf][0] = *(const uint32_t*)(pa);
                ah[mf][1] = *(const uint32_t*)(pa + 8 * GPITCH);
                ah[mf][2] = *(const uint32_t*)(pa + 16);
                ah[mf][3] = *(const uint32_t*)(pa + 8 * GPITCH + 16);
                al[mf][0] = *(const uint32_t*)(pa + ABYTES);
                al[mf][1] = *(const uint32_t*)(pa + ABYTES + 8 * GPITCH);
                al[mf][2] = *(const uint32_t*)(pa + ABYTES + 16);
                al[mf][3] = *(const uint32_t*)(pa + ABYTES + 8 * GPITCH + 16);
            }
            // B fragments (hi & lo), 4 n-frags of 8 cols
            uint32_t bh[4][2], bl[4][2];
#pragma unroll
            for (int nf = 0; nf < 4; nf++) {
                const char* pb = st + 2 * ABYTES
                               + (wn * 32 + nf * 8 + (lane >> 2)) * GPITCH
                               + kb + (lane & 3) * 4;
                bh[nf][0] = *(const uint32_t*)(pb);
                bh[nf][1] = *(const uint32_t*)(pb + 16);
                bl[nf][0] = *(const uint32_t*)(pb + BBYTES);
                bl[nf][1] = *(const uint32_t*)(pb + BBYTES + 16);
            }
            // 3 passes: Ah*Bh + Al*Bh + Ah*Bl
#pragma unroll
            for (int mf = 0; mf < 2; mf++)
#pragma unroll
                for (int nf = 0; nf < 4; nf++) {
                    MMA16816(acc[mf][nf], ah[mf], bh[nf]);
                    MMA16816(acc[mf][nf], al[mf], bh[nf]);
                    MMA16816(acc[mf][nf], ah[mf], bl[nf]);
                }
        }
        __syncthreads();
    }

    // ---- epilogue ----
#pragma unroll
    for (int mf = 0; mf < 2; mf++) {
        int r0 = m0 + wm * 32 + mf * 16 + (lane >> 2);
#pragma unroll
        for (int nf = 0; nf < 4; nf++) {
            int col = n0 + wn * 32 + nf * 8 + (lane & 3) * 2;
            if (r0 < M) {
                float2 v = make_float2(acc[mf][nf][0], acc[mf][nf][1]);
                *(float2*)(C + (size_t)r0 * Ntot + col) = v;
            }
            if (r0 + 8 < M) {
                float2 v = make_float2(acc[mf][nf][2], acc[mf][nf][3]);
                *(float2*)(C + (size_t)(r0 + 8) * Ntot + col) = v;
            }
        }
    }
}

// ---------------- layer-1 attention dots ----------------
__global__ void k_attn1(const float* __restrict__ a_src, const float* __restrict__ a_dst) {
    int n = blockIdx.x;
    int w = threadIdx.x >> 5;
    int lane = threadIdx.x & 31;
    const float* hrow = g_h1 + (size_t)n * F1 + w * HID;
    float s = 0.f, d = 0.f;
#pragma unroll
    for (int c = lane; c < HID; c += 32) {
        float hv = hrow[c];
        s += hv * a_src[w * HID + c];
        d += hv * a_dst[w * HID + c];
    }
#pragma unroll
    for (int off = 16; off > 0; off >>= 1) {
        s += __shfl_xor_sync(0xffffffffu, s, off);
        d += __shfl_xor_sync(0xffffffffu, d, off);
    }
    if (lane == 0) { g_as1[n * HEADS + w] = s; g_ad1[n * HEADS + w] = d; }
}

// ---------------- layer-1 edge softmax ----------------
__global__ void k_softmax1() {
    int idx = blockIdx.x * 256 + threadIdx.x;
    if (idx >= N_NODES * HEADS) return;
    int n = idx >> 3, h = idx & 7;
    int beg = g_rowptr[n], end = g_rowptr[n + 1];
    float adv = g_ad1[idx];
    float m = -1e30f;
    for (int p = beg; p < end; p++) {
        float l = g_as1[g_csrsrc[p] * HEADS + h] + adv;
        l = (l > 0.f) ? l : NEG * l;
        m = fmaxf(m, l);
    }
    float z = 0.f;
    for (int p = beg; p < end; p++) {
        float l = g_as1[g_csrsrc[p] * HEADS + h] + adv;
        l = (l > 0.f) ? l : NEG * l;
        float e = __expf(l - m);
        g_alpha1[(size_t)p * HEADS + h] = e;
        z += e;
    }
    float inv = 1.f / z;
    for (int p = beg; p < end; p++) g_alpha1[(size_t)p * HEADS + h] *= inv;
}

// ---------------- layer-1 aggregation + bias + ELU + bf16 split ----------------
__global__ void k_agg1(const float* __restrict__ b1) {
    int n = blockIdx.x;
    int tid = threadIdx.x;        // h*128 + c
    int h = tid >> 7;
    int beg = g_rowptr[n], end = g_rowptr[n + 1];
    float acc = 0.f;
    int p = beg;
    for (; p + 4 <= end; p += 4) {
        int s0 = g_csrsrc[p], s1 = g_csrsrc[p + 1], s2 = g_csrsrc[p + 2], s3 = g_csrsrc[p + 3];
        float a0 = g_alpha1[(size_t)(p    ) * HEADS + h];
        float a1 = g_alpha1[(size_t)(p + 1) * HEADS + h];
        float a2 = g_alpha1[(size_t)(p + 2) * HEADS + h];
        float a3 = g_alpha1[(size_t)(p + 3) * HEADS + h];
        float v0 = g_h1[(size_t)s0 * F1 + tid];
        float v1 = g_h1[(size_t)s1 * F1 + tid];
        float v2 = g_h1[(size_t)s2 * F1 + tid];
        float v3 = g_h1[(size_t)s3 * F1 + tid];
        acc += a0 * v0; acc += a1 * v1; acc += a2 * v2; acc += a3 * v3;
    }
    for (; p < end; p++) {
        acc += g_alpha1[(size_t)p * HEADS + h] * g_h1[(size_t)g_csrsrc[p] * F1 + tid];
    }
    float v = acc + b1[tid];
    v = (v > 0.f) ? v : (expf(v) - 1.f);   // ELU
    size_t oi = (size_t)n * F1 + tid;
    __nv_bfloat16 hi = __float2bfloat16(v);
    g_h2h[oi] = hi;
    g_h2l[oi] = __float2bfloat16(v - __bfloat162float(hi));
}

// ---------------- layer-2 attention dots ----------------
__global__ void k_attn2(const float* __restrict__ a_src, const float* __restrict__ a_dst) {
    int n = blockIdx.x * 8 + (threadIdx.x >> 5);
    if (n >= N_NODES) return;
    int lane = threadIdx.x & 31;
    const float* grow = g_g2 + (size_t)n * OUT_C;
    float s = 0.f, d = 0.f;
#pragma unroll
    for (int c = lane; c < OUT_C; c += 32) {
        float gv = grow[c];
        s += gv * a_src[c];
        d += gv * a_dst[c];
    }
#pragma unroll
    for (int off = 16; off > 0; off >>= 1) {
        s += __shfl_xor_sync(0xffffffffu, s, off);
        d += __shfl_xor_sync(0xffffffffu, d, off);
    }
    if (lane == 0) { g_as2[n] = s; g_ad2[n] = d; }
}

// ---------------- layer-2 edge softmax ----------------
__global__ void k_softmax2() {
    int n = blockIdx.x * 256 + threadIdx.x;
    if (n >= N_NODES) return;
    int beg = g_rowptr[n], end = g_rowptr[n + 1];
    float adv = g_ad2[n];
    float m = -1e30f;
    for (int p = beg; p < end; p++) {
        float l = g_as2[g_csrsrc[p]] + adv;
        l = (l > 0.f) ? l : NEG * l;
        m = fmaxf(m, l);
    }
    float z = 0.f;
    for (int p = beg; p < end; p++) {
        float l = g_as2[g_csrsrc[p]] + adv;
        l = (l > 0.f) ? l : NEG * l;
        float e = __expf(l - m);
        g_alpha2[p] = e;
        z += e;
    }
    float inv = 1.f / z;
    for (int p = beg; p < end; p++) g_alpha2[p] *= inv;
}

// ---------------- layer-2 aggregation ----------------
__global__ void k_agg2() {
    int n = blockIdx.x;
    int tid = threadIdx.x;        // 0..63
    int beg = g_rowptr[n], end = g_rowptr[n + 1];
    float acc = 0.f;
    int p = beg;
    for (; p + 4 <= end; p += 4) {
        int s0 = g_csrsrc[p], s1 = g_csrsrc[p + 1], s2 = g_csrsrc[p + 2], s3 = g_csrsrc[p + 3];
        float a0 = g_alpha2[p], a1 = g_alpha2[p + 1], a2 = g_alpha2[p + 2], a3 = g_alpha2[p + 3];
        float v0 = g_g2[(size_t)s0 * OUT_C + tid];
        float v1 = g_g2[(size_t)s1 * OUT_C + tid];
        float v2 = g_g2[(size_t)s2 * OUT_C + tid];
        float v3 = g_g2[(size_t)s3 * OUT_C + tid];
        acc += a0 * v0; acc += a1 * v1; acc += a2 * v2; acc += a3 * v3;
    }
    for (; p < end; p++) {
        acc += g_alpha2[p] * g_g2[(size_t)g_csrsrc[p] * OUT_C + tid];
    }
    g_out2[(size_t)n * OUT_C + tid] = acc;
}

// ---------------- bias + log_softmax ----------------
__global__ void k_logsoftmax(const float* __restrict__ b2, float* __restrict__ out) {
    int n = blockIdx.x * 8 + (threadIdx.x >> 5);
    if (n >= N_NODES) return;
    int lane = threadIdx.x & 31;
    float v0 = g_out2[(size_t)n * OUT_C + lane]      + b2[lane];
    float v1 = g_out2[(size_t)n * OUT_C + 32 + lane] + b2[32 + lane];
    float m = fmaxf(v0, v1);
#pragma unroll
    for (int off = 16; off > 0; off >>= 1) m = fmaxf(m, __shfl_xor_sync(0xffffffffu, m, off));
    float s = expf(v0 - m) + expf(v1 - m);
#pragma unroll
    for (int off = 16; off > 0; off >>= 1) s += __shfl_xor_sync(0xffffffffu, s, off);
    float ls = logf(s);
    out[(size_t)n * OUT_C + lane]      = v0 - m - ls;
    out[(size_t)n * OUT_C + 32 + lane] = v1 - m - ls;
}

// ---------------- launch ----------------
extern "C" void kernel_launch(void* const* d_in, const int* in_sizes, int n_in,
                              void* d_out, int out_size) {
    const float* x     = (const float*)d_in[0];
    const int*   ei    = (const int*)  d_in[1];
    const float* W1    = (const float*)d_in[2];
    const float* asrc1 = (const float*)d_in[3];
    const float* adst1 = (const float*)d_in[4];
    const float* b1    = (const float*)d_in[5];
    const float* W2    = (const float*)d_in[6];
    const float* asrc2 = (const float*)d_in[7];
    const float* adst2 = (const float*)d_in[8];
    const float* b2    = (const float*)d_in[9];
    float* out = (float*)d_out;

    void *p_h1, *p_g2, *p_xh, *p_xl, *p_h2h, *p_h2l, *p_w1h, *p_w1l, *p_w2h, *p_w2l;
    cudaGetSymbolAddress(&p_h1,  g_h1);
    cudaGetSymbolAddress(&p_g2,  g_g2);
    cudaGetSymbolAddress(&p_xh,  g_xh);
    cudaGetSymbolAddress(&p_xl,  g_xl);
    cudaGetSymbolAddress(&p_h2h, g_h2h);
    cudaGetSymbolAddress(&p_h2l, g_h2l);
    cudaGetSymbolAddress(&p_w1h, g_W1th);
    cudaGetSymbolAddress(&p_w1l, g_W1tl);
    cudaGetSymbolAddress(&p_w2h, g_W2th);
    cudaGetSymbolAddress(&p_w2l, g_W2tl);

    cudaFuncSetAttribute(gemm_mma, cudaFuncAttributeMaxDynamicSharedMemorySize, GSMEM);

    const int TPB = 256;
    // CSR build (dst-sorted)
    k_zero_deg<<<(N_NODES + TPB - 1) / TPB, TPB>>>();
    k_count  <<<(E_TOT   + TPB - 1) / TPB, TPB>>>(ei);
    k_scan   <<<1, 1024>>>();
    k_cursor <<<(N_NODES + TPB - 1) / TPB, TPB>>>();
    k_scatter<<<(E_TOT   + TPB - 1) / TPB, TPB>>>(ei);

    // operand prep
    k_split_x<<<(int)(((size_t)N_NODES * IN_C + TPB - 1) / TPB), TPB>>>(x);
    k_split_wt<<<(int)(((size_t)IN_C * F1 + TPB - 1) / TPB), TPB>>>(
        W1, (__nv_bfloat16*)p_w1h, (__nv_bfloat16*)p_w1l, IN_C, F1);
    k_split_wt<<<(int)(((size_t)F1 * OUT_C + TPB - 1) / TPB), TPB>>>(
        W2, (__nv_bfloat16*)p_w2h, (__nv_bfloat16*)p_w2l, F1, OUT_C);

    // layer 1: h1 = x @ W1 (warp-MMA bf16, 3-pass split)
    gemm_mma<<<dim3(F1 / 64, (N_NODES + 127) / 128), 256, GSMEM>>>(
        (const __nv_bfloat16*)p_xh, (const __nv_bfloat16*)p_xl,
        (const __nv_bfloat16*)p_w1h, (const __nv_bfloat16*)p_w1l,
        (float*)p_h1, N_NODES, F1, IN_C);
    k_attn1<<<N_NODES, 256>>>(asrc1, adst1);
    k_softmax1<<<(N_NODES * HEADS + TPB - 1) / TPB, TPB>>>();
    k_agg1<<<N_NODES, 1024>>>(b1);

    // layer 2: g2 = h2 @ W2 (warp-MMA bf16, 3-pass split)
    gemm_mma<<<dim3(OUT_C / 64, (N_NODES + 127) / 128), 256, GSMEM>>>(
        (const __nv_bfloat16*)p_h2h, (const __nv_bfloat16*)p_h2l,
        (const __nv_bfloat16*)p_w2h, (const __nv_bfloat16*)p_w2l,
        (float*)p_g2, N_NODES, OUT_C, F1);
    k_attn2<<<(N_NODES + 7) / 8, 256>>>(asrc2, adst2);
    k_softmax2<<<(N_NODES + TPB - 1) / TPB, TPB>>>();
    k_agg2<<<N_NODES, 64>>>();
    k_logsoftmax<<<(N_NODES + 7) / 8, 256>>>(b2, out);
}

// round 6
// speedup vs baseline: 3.0179x; 2.3076x over previous
#include <cuda_runtime.h>
#include <cuda_bf16.h>
#include <math.h>
#include <stdint.h>

#define N_NODES 50000
#define E_EDGES 1600000
#define E_TOT   (E_EDGES + N_NODES)
#define HEADS   8
#define HID     128
#define IN_C    512
#define F1      (HEADS*HID)   /* 1024 */
#define OUT_C   64
#define NEG     0.2f

// ---------------- scratch (device globals: allocation-free) ----------------
__device__ __nv_bfloat162 g_h1b[(size_t)N_NODES * (F1/2)];   // layer1 features bf16 pairs
__device__ __nv_bfloat162 g_h2b[(size_t)N_NODES * (F1/2)];   // elu(agg1+b1) bf16 pairs
__device__ float g_as1[N_NODES * HEADS];
__device__ float g_ad1[N_NODES * HEADS];
__device__ float g_g2[(size_t)N_NODES * OUT_C];
__device__ float g_as2[N_NODES];
__device__ float g_ad2[N_NODES];
__device__ int   g_deg[N_NODES];
__device__ int   g_rowptr[N_NODES + 1];
__device__ int   g_cursor[N_NODES];
__device__ int   g_csrsrc[E_TOT];

// bf16 operands for tensor-core GEMMs
__device__ __nv_bfloat16 g_xb[(size_t)N_NODES * IN_C];
__device__ __nv_bfloat16 g_W1t[(size_t)F1 * IN_C];   // [n][k] K-major transposed
__device__ __nv_bfloat16 g_W2t[(size_t)OUT_C * F1];

// ---------------- helpers ----------------
__device__ __forceinline__ uint32_t smem_u32(const void* p) {
    uint32_t a;
    asm("{ .reg .u64 t; cvta.to.shared.u64 t, %1; cvt.u32.u64 %0, t; }" : "=r"(a) : "l"(p));
    return a;
}
#define CP16(sa, ga) \
    asm volatile("cp.async.cg.shared.global [%0], [%1], 16;" :: "r"(sa), "l"(ga))
#define CP_COMMIT() asm volatile("cp.async.commit_group;" ::: "memory")
#define CP_WAIT1()  asm volatile("cp.async.wait_group 1;" ::: "memory")
#define CP_WAIT0()  asm volatile("cp.async.wait_group 0;" ::: "memory")

#define MMA16816(c, a, b)                                                      \
    asm volatile("mma.sync.aligned.m16n8k16.row.col.f32.bf16.bf16.f32 "        \
                 "{%0,%1,%2,%3}, {%4,%5,%6,%7}, {%8,%9}, {%0,%1,%2,%3};"       \
                 : "+f"((c)[0]), "+f"((c)[1]), "+f"((c)[2]), "+f"((c)[3])      \
                 : "r"((a)[0]), "r"((a)[1]), "r"((a)[2]), "r"((a)[3]),         \
                   "r"((b)[0]), "r"((b)[1]))

// ---------------- CSR build ----------------
__global__ void k_zero_deg() {
    int i = blockIdx.x * 256 + threadIdx.x;
    if (i < N_NODES) g_deg[i] = 0;
}
__global__ void k_count(const int* __restrict__ ei) {
    int e = blockIdx.x * 256 + threadIdx.x;
    if (e >= E_TOT) return;
    int dst = (e < E_EDGES) ? ei[E_EDGES + e] : (e - E_EDGES);
    atomicAdd(&g_deg[dst], 1);
}
__global__ void k_scan() {
    __shared__ int sh[1024];
    int t = threadIdx.x;
    const int chunk = (N_NODES + 1023) / 1024;
    int beg = t * chunk, end = min(beg + chunk, N_NODES);
    int sum = 0;
    for (int i = beg; i < end; i++) sum += g_deg[i];
    sh[t] = sum;
    __syncthreads();
    for (int off = 1; off < 1024; off <<= 1) {
        int v = (t >= off) ? sh[t - off] : 0;
        __syncthreads();
        sh[t] += v;
        __syncthreads();
    }
    int run = sh[t] - sum;
    for (int i = beg; i < end; i++) { g_rowptr[i] = run; run += g_deg[i]; }
    if (t == 1023) g_rowptr[N_NODES] = sh[1023];
}
__global__ void k_cursor() {
    int i = blockIdx.x * 256 + threadIdx.x;
    if (i < N_NODES) g_cursor[i] = g_rowptr[i];
}
__global__ void k_scatter(const int* __restrict__ ei) {
    int e = blockIdx.x * 256 + threadIdx.x;
    if (e >= E_TOT) return;
    int src, dst;
    if (e < E_EDGES) { src = ei[e]; dst = ei[E_EDGES + e]; }
    else             { src = e - E_EDGES; dst = src; }
    int pos = atomicAdd(&g_cursor[dst], 1);
    g_csrsrc[pos] = src;
}

// ---------------- bf16 conversion of x ----------------
__global__ void k_split_x(const float* __restrict__ x) {
    size_t i = (size_t)blockIdx.x * 256 + threadIdx.x;
    if (i >= (size_t)N_NODES * IN_C) return;
    g_xb[i] = __float2bfloat16(x[i]);
}

// transpose W: W[K][N] -> T[n][k] bf16
__global__ void k_split_wt(const float* __restrict__ W, __nv_bfloat16* __restrict__ T,
                           int K, int N) {
    size_t i = (size_t)blockIdx.x * 256 + threadIdx.x;
    if (i >= (size_t)K * N) return;
    int n = (int)(i / K), k = (int)(i % K);
    T[i] = __float2bfloat16(W[(size_t)k * N + n]);
}

// ---------------- warp-MMA bf16 single-pass GEMM ----------------
// C[M,Ntot] = A[M,K] @ B^T, B stored K-major [Ntot][K].
// CTA tile 128x64, BK=32, 8 warps (4x2), warp tile 32x32. Double-buffered cp.async.
#define GPITCH 112
#define ABYTES (128 * GPITCH)
#define BBYTES (64 * GPITCH)
#define STG    (ABYTES + BBYTES)   /* 21504 */
#define GSMEM  (2 * STG)           /* 43008 */

template <bool OUT_BF16>
__global__ __launch_bounds__(256, 4)
void gemm_mma(const __nv_bfloat16* __restrict__ A, const __nv_bfloat16* __restrict__ B,
              void* __restrict__ Cout, int M, int Ntot, int K) {
    extern __shared__ __align__(16) char smraw[];
    uint32_t sbase = smem_u32(smraw);

    int tid = threadIdx.x;
    int lane = tid & 31, wid = tid >> 5;
    int wm = wid >> 1, wn = wid & 1;
    int m0 = blockIdx.y * 128;
    int n0 = blockIdx.x * 64;
    int KT = K >> 5;

    auto load_tile = [&](int kt, int s) {
        int k0 = kt << 5;
        uint32_t st = sbase + s * STG;
        // A: 128 rows x 4 chunks of 16B = 512 chunks
#pragma unroll
        for (int i = 0; i < 2; i++) {
            int c = tid + i * 256;
            int r = c >> 2, cg = c & 3;
            int gr = m0 + r; if (gr >= M) gr = M - 1;
            const char* ga = (const char*)(A + (size_t)gr * K + k0) + cg * 16;
            CP16(st + r * GPITCH + cg * 16, ga);
        }
        // B: 64 rows x 4 chunks = 256 chunks
        {
            int r = tid >> 2, cg = tid & 3;
            const char* gb = (const char*)(B + (size_t)(n0 + r) * K + k0) + cg * 16;
            CP16(st + ABYTES + r * GPITCH + cg * 16, gb);
        }
    };

    float acc[2][4][4];
#pragma unroll
    for (int i = 0; i < 2; i++)
#pragma unroll
        for (int j = 0; j < 4; j++)
#pragma unroll
            for (int q = 0; q < 4; q++) acc[i][j][q] = 0.f;

    load_tile(0, 0);
    CP_COMMIT();

    for (int kt = 0; kt < KT; kt++) {
        int cur = kt & 1;
        if (kt + 1 < KT) { load_tile(kt + 1, cur ^ 1); CP_COMMIT(); CP_WAIT1(); }
        else             { CP_WAIT0(); }
        __syncthreads();

        const char* st = smraw + cur * STG;
#pragma unroll
        for (int ks = 0; ks < 2; ks++) {
            int kb = ks * 32;
            uint32_t ah[2][4];
#pragma unroll
            for (int mf = 0; mf < 2; mf++) {
                const char* pa = st + (wm * 32 + mf * 16 + (lane >> 2)) * GPITCH
                               + kb + (lane & 3) * 4;
                ah[mf][0] = *(const uint32_t*)(pa);
                ah[mf][1] = *(const uint32_t*)(pa + 8 * GPITCH);
                ah[mf][2] = *(const uint32_t*)(pa + 16);
                ah[mf][3] = *(const uint32_t*)(pa + 8 * GPITCH + 16);
            }
            uint32_t bh[4][2];
#pragma unroll
            for (int nf = 0; nf < 4; nf++) {
                const char* pb = st + ABYTES
                               + (wn * 32 + nf * 8 + (lane >> 2)) * GPITCH
                               + kb + (lane & 3) * 4;
                bh[nf][0] = *(const uint32_t*)(pb);
                bh[nf][1] = *(const uint32_t*)(pb + 16);
            }
#pragma unroll
            for (int mf = 0; mf < 2; mf++)
#pragma unroll
                for (int nf = 0; nf < 4; nf++)
                    MMA16816(acc[mf][nf], ah[mf], bh[nf]);
        }
        __syncthreads();
    }

    // ---- epilogue ----
#pragma unroll
    for (int mf = 0; mf < 2; mf++) {
        int r0 = m0 + wm * 32 + mf * 16 + (lane >> 2);
#pragma unroll
        for (int nf = 0; nf < 4; nf++) {
            int col = n0 + wn * 32 + nf * 8 + (lane & 3) * 2;
            if (OUT_BF16) {
                __nv_bfloat162* Cb = (__nv_bfloat162*)Cout;
                if (r0 < M)
                    Cb[((size_t)r0 * Ntot + col) >> 1] =
                        __floats2bfloat162_rn(acc[mf][nf][0], acc[mf][nf][1]);
                if (r0 + 8 < M)
                    Cb[((size_t)(r0 + 8) * Ntot + col) >> 1] =
                        __floats2bfloat162_rn(acc[mf][nf][2], acc[mf][nf][3]);
            } else {
                float* Cf = (float*)Cout;
                if (r0 < M)
                    *(float2*)(Cf + (size_t)r0 * Ntot + col) =
                        make_float2(acc[mf][nf][0], acc[mf][nf][1]);
                if (r0 + 8 < M)
                    *(float2*)(Cf + (size_t)(r0 + 8) * Ntot + col) =
                        make_float2(acc[mf][nf][2], acc[mf][nf][3]);
            }
        }
    }
}

// ---------------- layer-1 attention dots (from bf16 h1) ----------------
__global__ void k_attn1(const float* __restrict__ a_src, const float* __restrict__ a_dst) {
    int n = blockIdx.x;
    int w = threadIdx.x >> 5;     // head
    int lane = threadIdx.x & 31;
    const __nv_bfloat162* hr = g_h1b + (size_t)n * (F1/2) + w * (HID/2);
    float s = 0.f, d = 0.f;
#pragma unroll
    for (int i = lane; i < HID/2; i += 32) {
        float2 hv = __bfloat1622float2(hr[i]);
        s += hv.x * a_src[w * HID + 2*i] + hv.y * a_src[w * HID + 2*i + 1];
        d += hv.x * a_dst[w * HID + 2*i] + hv.y * a_dst[w * HID + 2*i + 1];
    }
#pragma unroll
    for (int off = 16; off > 0; off >>= 1) {
        s += __shfl_xor_sync(0xffffffffu, s, off);
        d += __shfl_xor_sync(0xffffffffu, d, off);
    }
    if (lane == 0) { g_as1[n * HEADS + w] = s; g_ad1[n * HEADS + w] = d; }
}

// ---------------- layer-1 fused edge-softmax + aggregation + bias + ELU ----------------
// Block = 512 threads, one dst node per block. Thread t owns channels 2t,2t+1; head = t>>6.
__global__ __launch_bounds__(512)
void k_agg1f(const float* __restrict__ b1) {
    __shared__ int   sh_src[64];
    __shared__ float sh_e[64 * 8];
    __shared__ float sh_z[8];
    int n = blockIdx.x;
    int t = threadIdx.x;
    int lane = t & 31;
    int ht = t >> 6;
    if (t < 8) sh_z[t] = 0.f;
    int beg = g_rowptr[n], end = g_rowptr[n + 1];
    float2 acc = make_float2(0.f, 0.f);

    for (int c0 = beg; c0 < end; c0 += 64) {
        int cnt = min(64, end - c0);
        __syncthreads();
        if (t < cnt) sh_src[t] = g_csrsrc[c0 + t];
        __syncthreads();
        // compute e for cnt edges x 8 heads (threads t = j*8+h)
        {
            float e = 0.f;
            int h = t & 7;
            if (t < cnt * 8) {
                int j = t >> 3;
                int s = sh_src[j];
                float l = g_as1[s * 8 + h] + g_ad1[n * 8 + h];
                l = (l > 0.f) ? l : NEG * l;
                e = __expf(l);
                sh_e[t] = e;
            }
            // warp-segmented reduce over lanes with same h (xor 8, 16)
            float ez = e;
            ez += __shfl_xor_sync(0xffffffffu, ez, 8);
            ez += __shfl_xor_sync(0xffffffffu, ez, 16);
            if ((lane >> 3) == 0) atomicAdd(&sh_z[h], ez);
        }
        __syncthreads();
        int j = 0;
        for (; j + 4 <= cnt; j += 4) {
            int s0 = sh_src[j], s1 = sh_src[j+1], s2 = sh_src[j+2], s3 = sh_src[j+3];
            float e0 = sh_e[j*8 + ht],      e1 = sh_e[j*8 + 8 + ht];
            float e2 = sh_e[j*8 + 16 + ht], e3 = sh_e[j*8 + 24 + ht];
            float2 v0 = __bfloat1622float2(g_h1b[(size_t)s0 * (F1/2) + t]);
            float2 v1 = __bfloat1622float2(g_h1b[(size_t)s1 * (F1/2) + t]);
            float2 v2 = __bfloat1622float2(g_h1b[(size_t)s2 * (F1/2) + t]);
            float2 v3 = __bfloat1622float2(g_h1b[(size_t)s3 * (F1/2) + t]);
            acc.x += e0 * v0.x + e1 * v1.x + e2 * v2.x + e3 * v3.x;
            acc.y += e0 * v0.y + e1 * v1.y + e2 * v2.y + e3 * v3.y;
        }
        for (; j < cnt; j++) {
            float e = sh_e[j*8 + ht];
            float2 v = __bfloat1622float2(g_h1b[(size_t)sh_src[j] * (F1/2) + t]);
            acc.x += e * v.x;
            acc.y += e * v.y;
        }
    }
    __syncthreads();
    float inv = 1.f / sh_z[ht];
    float2 bb = *(const float2*)(b1 + 2 * t);
    float vx = acc.x * inv + bb.x;
    float vy = acc.y * inv + bb.y;
    vx = (vx > 0.f) ? vx : (expf(vx) - 1.f);
    vy = (vy > 0.f) ? vy : (expf(vy) - 1.f);
    g_h2b[(size_t)n * (F1/2) + t] = __floats2bfloat162_rn(vx, vy);
}

// ---------------- layer-2 attention dots ----------------
__global__ void k_attn2(const float* __restrict__ a_src, const float* __restrict__ a_dst) {
    int n = blockIdx.x * 8 + (threadIdx.x >> 5);
    if (n >= N_NODES) return;
    int lane = threadIdx.x & 31;
    const float* grow = g_g2 + (size_t)n * OUT_C;
    float s = 0.f, d = 0.f;
#pragma unroll
    for (int c = lane; c < OUT_C; c += 32) {
        float gv = grow[c];
        s += gv * a_src[c];
        d += gv * a_dst[c];
    }
#pragma unroll
    for (int off = 16; off > 0; off >>= 1) {
        s += __shfl_xor_sync(0xffffffffu, s, off);
        d += __shfl_xor_sync(0xffffffffu, d, off);
    }
    if (lane == 0) { g_as2[n] = s; g_ad2[n] = d; }
}

// ---------------- layer-2 fused softmax + aggregation + bias + log_softmax ----------------
// Block = 64 threads, one dst node per block. Thread t owns class t.
__global__ __launch_bounds__(64)
void k_agg2f(const float* __restrict__ b2, float* __restrict__ out) {
    __shared__ int   sh_src[64];
    __shared__ float sh_e[64];
    __shared__ float sh_z;
    __shared__ float red[2];
    int n = blockIdx.x;
    int t = threadIdx.x;
    int lane = t & 31, wrp = t >> 5;
    if (t == 0) sh_z = 0.f;
    int beg = g_rowptr[n], end = g_rowptr[n + 1];
    float acc = 0.f;
    float adv = g_ad2[n];

    for (int c0 = beg; c0 < end; c0 += 64) {
        int cnt = min(64, end - c0);
        __syncthreads();
        if (t < cnt) sh_src[t] = g_csrsrc[c0 + t];
        __syncthreads();
        {
            float e = 0.f;
            if (t < cnt) {
                float l = g_as2[sh_src[t]] + adv;
                l = (l > 0.f) ? l : NEG * l;
                e = __expf(l);
                sh_e[t] = e;
            }
            float ez = e;
#pragma unroll
            for (int off = 16; off > 0; off >>= 1) ez += __shfl_xor_sync(0xffffffffu, ez, off);
            if (lane == 0) atomicAdd(&sh_z, ez);
        }
        __syncthreads();
        int j = 0;
        for (; j + 4 <= cnt; j += 4) {
            int s0 = sh_src[j], s1 = sh_src[j+1], s2 = sh_src[j+2], s3 = sh_src[j+3];
            float e0 = sh_e[j], e1 = sh_e[j+1], e2 = sh_e[j+2], e3 = sh_e[j+3];
            acc += e0 * g_g2[(size_t)s0 * OUT_C + t];
            acc += e1 * g_g2[(size_t)s1 * OUT_C + t];
            acc += e2 * g_g2[(size_t)s2 * OUT_C + t];
            acc += e3 * g_g2[(size_t)s3 * OUT_C + t];
        }
        for (; j < cnt; j++)
            acc += sh_e[j] * g_g2[(size_t)sh_src[j] * OUT_C + t];
    }
    __syncthreads();
    float v = acc / sh_z + b2[t];
    // log_softmax over 64 classes (2 warps)
    float m = v;
#pragma unroll
    for (int off = 16; off > 0; off >>= 1) m = fmaxf(m, __shfl_xor_sync(0xffffffffu, m, off));
    if (lane == 0) red[wrp] = m;
    __syncthreads();
    m = fmaxf(red[0], red[1]);
    float s = expf(v - m);
#pragma unroll
    for (int off = 16; off > 0; off >>= 1) s += __shfl_xor_sync(0xffffffffu, s, off);
    __syncthreads();
    if (lane == 0) red[wrp] = s;
    __syncthreads();
    s = red[0] + red[1];
    out[(size_t)n * OUT_C + t] = v - m - logf(s);
}

// ---------------- launch ----------------
extern "C" void kernel_launch(void* const* d_in, const int* in_sizes, int n_in,
                              void* d_out, int out_size) {
    const float* x     = (const float*)d_in[0];
    const int*   ei    = (const int*)  d_in[1];
    const float* W1    = (const float*)d_in[2];
    const float* asrc1 = (const float*)d_in[3];
    const float* adst1 = (const float*)d_in[4];
    const float* b1    = (const float*)d_in[5];
    const float* W2    = (const float*)d_in[6];
    const float* asrc2 = (const float*)d_in[7];
    const float* adst2 = (const float*)d_in[8];
    const float* b2    = (const float*)d_in[9];
    float* out = (float*)d_out;

    void *p_h1b, *p_h2b, *p_g2, *p_xb, *p_w1t, *p_w2t;
    cudaGetSymbolAddress(&p_h1b, g_h1b);
    cudaGetSymbolAddress(&p_h2b, g_h2b);
    cudaGetSymbolAddress(&p_g2,  g_g2);
    cudaGetSymbolAddress(&p_xb,  g_xb);
    cudaGetSymbolAddress(&p_w1t, g_W1t);
    cudaGetSymbolAddress(&p_w2t, g_W2t);

    cudaFuncSetAttribute(gemm_mma<true>,  cudaFuncAttributeMaxDynamicSharedMemorySize, GSMEM);
    cudaFuncSetAttribute(gemm_mma<false>, cudaFuncAttributeMaxDynamicSharedMemorySize, GSMEM);

    const int TPB = 256;
    // CSR build (dst-sorted)
    k_zero_deg<<<(N_NODES + TPB - 1) / TPB, TPB>>>();
    k_count  <<<(E_TOT   + TPB - 1) / TPB, TPB>>>(ei);
    k_scan   <<<1, 1024>>>();
    k_cursor <<<(N_NODES + TPB - 1) / TPB, TPB>>>();
    k_scatter<<<(E_TOT   + TPB - 1) / TPB, TPB>>>(ei);

    // operand prep (bf16)
    k_split_x<<<(int)(((size_t)N_NODES * IN_C + TPB - 1) / TPB), TPB>>>(x);
    k_split_wt<<<(int)(((size_t)IN_C * F1 + TPB - 1) / TPB), TPB>>>(
        W1, (__nv_bfloat16*)p_w1t, IN_C, F1);
    k_split_wt<<<(int)(((size_t)F1 * OUT_C + TPB - 1) / TPB), TPB>>>(
        W2, (__nv_bfloat16*)p_w2t, F1, OUT_C);

    // layer 1: h1 = x @ W1 (bf16 MMA, bf16 output)
    gemm_mma<true><<<dim3(F1 / 64, (N_NODES + 127) / 128), 256, GSMEM>>>(
        (const __nv_bfloat16*)p_xb, (const __nv_bfloat16*)p_w1t,
        p_h1b, N_NODES, F1, IN_C);
    k_attn1<<<N_NODES, 256>>>(asrc1, adst1);
    k_agg1f<<<N_NODES, 512>>>(b1);

    // layer 2: g2 = h2 @ W2 (bf16 MMA, fp32 output)
    gemm_mma<false><<<dim3(OUT_C / 64, (N_NODES + 127) / 128), 256, GSMEM>>>(
        (const __nv_bfloat16*)p_h2b, (const __nv_bfloat16*)p_w2t,
        p_g2, N_NODES, OUT_C, F1);
    k_attn2<<<(N_NODES + 7) / 8, 256>>>(asrc2, adst2);
    k_agg2f<<<N_NODES, 64>>>(b2, out);
}

// round 7
// speedup vs baseline: 3.3807x; 1.1202x over previous
#include <cuda_runtime.h>
#include <cuda_bf16.h>
#include <cuda_fp16.h>
#include <math.h>
#include <stdint.h>

#define N_NODES 50000
#define E_EDGES 1600000
#define E_TOT   (E_EDGES + N_NODES)
#define HEADS   8
#define HID     128
#define IN_C    512
#define F1      (HEADS*HID)   /* 1024 */
#define OUT_C   64
#define NEG     0.2f
#define H1SCALE 64.0f

// ---------------- scratch (device globals: allocation-free) ----------------
__device__ unsigned short g_h1f8[(size_t)N_NODES * (F1/2)];  // e4m3x2 pairs, scale 64
__device__ __nv_bfloat162 g_h2b[(size_t)N_NODES * (F1/2)];   // elu(agg1+b1) bf16 pairs
__device__ float g_asd[(size_t)N_NODES * 64];  // [n][0..7]=as1, [8..15]=ad1 (rest unused)
__device__ __nv_bfloat16 g_g2b[(size_t)N_NODES * OUT_C];
__device__ float g_as2[N_NODES];
__device__ float g_ad2[N_NODES];
__device__ int   g_deg[N_NODES];
__device__ int   g_rowptr[N_NODES + 1];
__device__ int   g_cursor[N_NODES];
__device__ int   g_csrsrc[E_TOT];
__device__ int   g_bsum[64];
__device__ int   g_boff[64];

// bf16 operands for tensor-core GEMMs
__device__ __nv_bfloat16 g_xb[(size_t)N_NODES * IN_C];
__device__ __nv_bfloat16 g_W1t[(size_t)F1 * IN_C];    // [n][k] K-major transposed
__device__ __nv_bfloat16 g_W2t[(size_t)OUT_C * F1];
__device__ __nv_bfloat16 g_Wab[(size_t)64 * IN_C];    // attn projection [64][512]

// ---------------- helpers ----------------
__device__ __forceinline__ uint32_t smem_u32(const void* p) {
    uint32_t a;
    asm("{ .reg .u64 t; cvta.to.shared.u64 t, %1; cvt.u32.u64 %0, t; }" : "=r"(a) : "l"(p));
    return a;
}
#define CP16(sa, ga) \
    asm volatile("cp.async.cg.shared.global [%0], [%1], 16;" :: "r"(sa), "l"(ga))
#define CP_COMMIT() asm volatile("cp.async.commit_group;" ::: "memory")
#define CP_WAIT1()  asm volatile("cp.async.wait_group 1;" ::: "memory")
#define CP_WAIT0()  asm volatile("cp.async.wait_group 0;" ::: "memory")

#define MMA16816(c, a, b)                                                      \
    asm volatile("mma.sync.aligned.m16n8k16.row.col.f32.bf16.bf16.f32 "        \
                 "{%0,%1,%2,%3}, {%4,%5,%6,%7}, {%8,%9}, {%0,%1,%2,%3};"       \
                 : "+f"((c)[0]), "+f"((c)[1]), "+f"((c)[2]), "+f"((c)[3])      \
                 : "r"((a)[0]), "r"((a)[1]), "r"((a)[2]), "r"((a)[3]),         \
                   "r"((b)[0]), "r"((b)[1]))

__device__ __forceinline__ unsigned short pack_e4m3x2(float lo, float hi) {
    unsigned short r;
    asm("cvt.rn.satfinite.e4m3x2.f32 %0, %1, %2;" : "=h"(r) : "f"(hi), "f"(lo));
    return r;
}
__device__ __forceinline__ float2 unpack_e4m3x2(unsigned short u) {
    uint32_t h2;
    asm("cvt.rn.f16x2.e4m3x2 %0, %1;" : "=r"(h2) : "h"(u));
    __half2 hh = *reinterpret_cast<__half2*>(&h2);
    return __half22float2(hh);
}

// ---------------- CSR build ----------------
__global__ void k_zero_deg() {
    int i = blockIdx.x * 256 + threadIdx.x;
    if (i < N_NODES) g_deg[i] = 0;
}
__global__ void k_count(const int* __restrict__ ei) {
    int e = blockIdx.x * 256 + threadIdx.x;
    if (e >= E_TOT) return;
    int dst = (e < E_EDGES) ? ei[E_EDGES + e] : (e - E_EDGES);
    atomicAdd(&g_deg[dst], 1);
}
// coalesced 3-phase exclusive scan of g_deg -> g_rowptr
__global__ void k_scan1() {
    __shared__ int sh[1024];
    int t = threadIdx.x, b = blockIdx.x;
    int i = b * 1024 + t;
    int v = (i < N_NODES) ? g_deg[i] : 0;
    sh[t] = v;
    __syncthreads();
    for (int off = 1; off < 1024; off <<= 1) {
        int u = (t >= off) ? sh[t - off] : 0;
        __syncthreads();
        sh[t] += u;
        __syncthreads();
    }
    if (i < N_NODES) g_rowptr[i + 1] = sh[t];
    if (t == 1023) g_bsum[b] = sh[1023];
}
__global__ void k_scan2(int nb) {
    if (threadIdx.x == 0) {
        int run = 0;
        for (int b = 0; b < nb; b++) { g_boff[b] = run; run += g_bsum[b]; }
    }
}
__global__ void k_scan3() {
    int t = threadIdx.x, b = blockIdx.x;
    int i = b * 1024 + t;
    if (i < N_NODES) g_rowptr[i + 1] += g_boff[b];
    if (i == 0) g_rowptr[0] = 0;
}
__global__ void k_cursor() {
    int i = blockIdx.x * 256 + threadIdx.x;
    if (i < N_NODES) g_cursor[i] = g_rowptr[i];
}
__global__ void k_scatter(const int* __restrict__ ei) {
    int e = blockIdx.x * 256 + threadIdx.x;
    if (e >= E_TOT) return;
    int src, dst;
    if (e < E_EDGES) { src = ei[e]; dst = ei[E_EDGES + e]; }
    else             { src = e - E_EDGES; dst = src; }
    int pos = atomicAdd(&g_cursor[dst], 1);
    g_csrsrc[pos] = src;
}

// ---------------- bf16 conversion of x ----------------
__global__ void k_split_x(const float* __restrict__ x) {
    size_t i = (size_t)blockIdx.x * 256 + threadIdx.x;
    if (i >= (size_t)N_NODES * IN_C) return;
    g_xb[i] = __float2bfloat16(x[i]);
}
// transpose W: W[K][N] -> T[n][k] bf16
__global__ void k_split_wt(const float* __restrict__ W, __nv_bfloat16* __restrict__ T,
                           int K, int N) {
    size_t i = (size_t)blockIdx.x * 256 + threadIdx.x;
    if (i >= (size_t)K * N) return;
    int n = (int)(i / K), k = (int)(i % K);
    T[i] = __float2bfloat16(W[(size_t)k * N + n]);
}
// attn projection: Wab[j][k] = sum_c W1t[(head*128+c)*512 + k] * a[head][c]
// j<8: a_src head j; j<16: a_dst head j-8; j>=16: 0.
__global__ void k_w1a(const float* __restrict__ a_src, const float* __restrict__ a_dst) {
    int j = blockIdx.x;             // 0..63
    int k = threadIdx.x;            // 0..511
    float acc = 0.f;
    if (j < 16) {
        int head = j & 7;
        const float* a = (j < 8) ? (a_src + head * HID) : (a_dst + head * HID);
        const __nv_bfloat16* wt = g_W1t + (size_t)(head * HID) * IN_C + k;
        for (int c = 0; c < HID; c++)
            acc += __bfloat162float(wt[(size_t)c * IN_C]) * a[c];
    }
    g_Wab[(size_t)j * IN_C + k] = __float2bfloat16(acc);
}

// ---------------- warp-MMA bf16 GEMM ----------------
// C[M,Ntot] = A[M,K] @ B^T, B stored K-major [Ntot][K].
// CTA tile 128xBN, BK=32, 8 warps (4x2), warp tile 32x(BN/2).
// MODE: 0 = fp32 out, 1 = bf16x2 out, 2 = e4m3 out (x H1SCALE, SMEM-staged)
#define GPITCH 112
#define GABYTES (128 * GPITCH)

template <int BN, int MODE>
__global__ __launch_bounds__(256, 2)
void gemm_mma(const __nv_bfloat16* __restrict__ A, const __nv_bfloat16* __restrict__ B,
              void* __restrict__ Cout, int M, int Ntot, int K) {
    constexpr int NF = BN / 16;                 // n-frags per warp
    constexpr int BBYTES = BN * GPITCH;
    constexpr int STG = GABYTES + BBYTES;
    extern __shared__ __align__(16) char smraw[];
    uint32_t sbase = smem_u32(smraw);

    int tid = threadIdx.x;
    int lane = tid & 31, wid = tid >> 5;
    int wm = wid >> 1, wn = wid & 1;
    int m0 = blockIdx.y * 128;
    int n0 = blockIdx.x * BN;
    int KT = K >> 5;

    auto load_tile = [&](int kt, int s) {
        int k0 = kt << 5;
        uint32_t st = sbase + s * STG;
#pragma unroll
        for (int i = 0; i < 2; i++) {           // A: 512 chunks
            int c = tid + i * 256;
            int r = c >> 2, cg = c & 3;
            int gr = m0 + r; if (gr >= M) gr = M - 1;
            const char* ga = (const char*)(A + (size_t)gr * K + k0) + cg * 16;
            CP16(st + r * GPITCH + cg * 16, ga);
        }
        for (int c = tid; c < BN * 4; c += 256) { // B: BN*4 chunks
            int r = c >> 2, cg = c & 3;
            const char* gb = (const char*)(B + (size_t)(n0 + r) * K + k0) + cg * 16;
            CP16(st + GABYTES + r * GPITCH + cg * 16, gb);
        }
    };

    float acc[2][NF][4];
#pragma unroll
    for (int i = 0; i < 2; i++)
#pragma unroll
        for (int j = 0; j < NF; j++)
#pragma unroll
            for (int q = 0; q < 4; q++) acc[i][j][q] = 0.f;

    load_tile(0, 0);
    CP_COMMIT();

    for (int kt = 0; kt < KT; kt++) {
        int cur = kt & 1;
        if (kt + 1 < KT) { load_tile(kt + 1, cur ^ 1); CP_COMMIT(); CP_WAIT1(); }
        else             { CP_WAIT0(); }
        __syncthreads();

        const char* st = smraw + cur * STG;
#pragma unroll
        for (int ks = 0; ks < 2; ks++) {
            int kb = ks * 32;
            uint32_t ah[2][4];
#pragma unroll
            for (int mf = 0; mf < 2; mf++) {
                const char* pa = st + (wm * 32 + mf * 16 + (lane >> 2)) * GPITCH
                               + kb + (lane & 3) * 4;
                ah[mf][0] = *(const uint32_t*)(pa);
                ah[mf][1] = *(const uint32_t*)(pa + 8 * GPITCH);
                ah[mf][2] = *(const uint32_t*)(pa + 16);
                ah[mf][3] = *(const uint32_t*)(pa + 8 * GPITCH + 16);
            }
            uint32_t bh[NF][2];
#pragma unroll
            for (int nf = 0; nf < NF; nf++) {
                const char* pb = st + GABYTES
                               + (wn * (BN/2) + nf * 8 + (lane >> 2)) * GPITCH
                               + kb + (lane & 3) * 4;
                bh[nf][0] = *(const uint32_t*)(pb);
                bh[nf][1] = *(const uint32_t*)(pb + 16);
            }
#pragma unroll
            for (int mf = 0; mf < 2; mf++)
#pragma unroll
                for (int nf = 0; nf < NF; nf++)
                    MMA16816(acc[mf][nf], ah[mf], bh[nf]);
        }
        __syncthreads();
    }

    // ---- epilogue ----
    if (MODE == 2) {
        // stage e4m3 pairs (scaled) in SMEM, then coalesced 16B stores
#pragma unroll
        for (int mf = 0; mf < 2; mf++) {
            int rl = wm * 32 + mf * 16 + (lane >> 2);
#pragma unroll
            for (int nf = 0; nf < NF; nf++) {
                int col = wn * (BN/2) + nf * 8 + (lane & 3) * 2;
                *(unsigned short*)(smraw + (size_t)rl * BN + col) =
                    pack_e4m3x2(acc[mf][nf][0] * H1SCALE, acc[mf][nf][1] * H1SCALE);
                *(unsigned short*)(smraw + (size_t)(rl + 8) * BN + col) =
                    pack_e4m3x2(acc[mf][nf][2] * H1SCALE, acc[mf][nf][3] * H1SCALE);
            }
        }
        __syncthreads();
        char* C8 = (char*)Cout;
        constexpr int CHUNKS = 128 * BN / 16;
        for (int c = tid; c < CHUNKS; c += 256) {
            int r = c / (BN / 16), g = c % (BN / 16);
            int gr = m0 + r;
            if (gr < M)
                *(uint4*)(C8 + (size_t)gr * Ntot + n0 + g * 16) =
                    *(const uint4*)(smraw + (size_t)r * BN + g * 16);
        }
    } else {
#pragma unroll
        for (int mf = 0; mf < 2; mf++) {
            int r0 = m0 + wm * 32 + mf * 16 + (lane >> 2);
#pragma unroll
            for (int nf = 0; nf < NF; nf++) {
                int col = n0 + wn * (BN/2) + nf * 8 + (lane & 3) * 2;
                if (MODE == 1) {
                    __nv_bfloat162* Cb = (__nv_bfloat162*)Cout;
                    if (r0 < M)
                        Cb[((size_t)r0 * Ntot + col) >> 1] =
                            __floats2bfloat162_rn(acc[mf][nf][0], acc[mf][nf][1]);
                    if (r0 + 8 < M)
                        Cb[((size_t)(r0 + 8) * Ntot + col) >> 1] =
                            __floats2bfloat162_rn(acc[mf][nf][2], acc[mf][nf][3]);
                } else {
                    float* Cf = (float*)Cout;
                    if (r0 < M)
                        *(float2*)(Cf + (size_t)r0 * Ntot + col) =
                            make_float2(acc[mf][nf][0], acc[mf][nf][1]);
                    if (r0 + 8 < M)
                        *(float2*)(Cf + (size_t)(r0 + 8) * Ntot + col) =
                            make_float2(acc[mf][nf][2], acc[mf][nf][3]);
                }
            }
        }
    }
}

// ---------------- layer-1 fused edge-softmax + aggregation + bias + ELU ----------------
// Block = 512 threads, one dst node per block. Thread t owns channels 2t,2t+1; head = t>>6.
__global__ __launch_bounds__(512)
void k_agg1f(const float* __restrict__ b1) {
    __shared__ int   sh_src[64];
    __shared__ float sh_e[64 * 8];
    __shared__ float sh_z[8];
    int n = blockIdx.x;
    int t = threadIdx.x;
    int lane = t & 31;
    int ht = t >> 6;
    if (t < 8) sh_z[t] = 0.f;
    int beg = g_rowptr[n], end = g_rowptr[n + 1];
    float2 acc = make_float2(0.f, 0.f);

    for (int c0 = beg; c0 < end; c0 += 64) {
        int cnt = min(64, end - c0);
        __syncthreads();
        if (t < cnt) sh_src[t] = g_csrsrc[c0 + t];
        __syncthreads();
        {
            float e = 0.f;
            int h = t & 7;
            if (t < cnt * 8) {
                int j = t >> 3;
                int s = sh_src[j];
                float l = g_asd[(size_t)s * 64 + h] + g_asd[(size_t)n * 64 + 8 + h];
                l = (l > 0.f) ? l : NEG * l;
                e = __expf(l);
                sh_e[t] = e;
            }
            float ez = e;
            ez += __shfl_xor_sync(0xffffffffu, ez, 8);
            ez += __shfl_xor_sync(0xffffffffu, ez, 16);
            if ((lane >> 3) == 0) atomicAdd(&sh_z[h], ez);
        }
        __syncthreads();
        int j = 0;
        for (; j + 4 <= cnt; j += 4) {
            int s0 = sh_src[j], s1 = sh_src[j+1], s2 = sh_src[j+2], s3 = sh_src[j+3];
            float e0 = sh_e[j*8 + ht],      e1 = sh_e[j*8 + 8 + ht];
            float e2 = sh_e[j*8 + 16 + ht], e3 = sh_e[j*8 + 24 + ht];
            float2 v0 = unpack_e4m3x2(g_h1f8[(size_t)s0 * (F1/2) + t]);
            float2 v1 = unpack_e4m3x2(g_h1f8[(size_t)s1 * (F1/2) + t]);
            float2 v2 = unpack_e4m3x2(g_h1f8[(size_t)s2 * (F1/2) + t]);
            float2 v3 = unpack_e4m3x2(g_h1f8[(size_t)s3 * (F1/2) + t]);
            acc.x += e0 * v0.x + e1 * v1.x + e2 * v2.x + e3 * v3.x;
            acc.y += e0 * v0.y + e1 * v1.y + e2 * v2.y + e3 * v3.y;
        }
        for (; j < cnt; j++) {
            float e = sh_e[j*8 + ht];
            float2 v = unpack_e4m3x2(g_h1f8[(size_t)sh_src[j] * (F1/2) + t]);
            acc.x += e * v.x;
            acc.y += e * v.y;
        }
    }
    __syncthreads();
    float inv = 1.f / (sh_z[ht] * H1SCALE);   // undo fp8 scale + softmax normalize
    float2 bb = *(const float2*)(b1 + 2 * t);
    float vx = acc.x * inv + bb.x;
    float vy = acc.y * inv + bb.y;
    vx = (vx > 0.f) ? vx : (expf(vx) - 1.f);
    vy = (vy > 0.f) ? vy : (expf(vy) - 1.f);
    g_h2b[(size_t)n * (F1/2) + t] = __floats2bfloat162_rn(vx, vy);
}

// ---------------- layer-2 attention dots (bf16 g2) ----------------
__global__ void k_attn2(const float* __restrict__ a_src, const float* __restrict__ a_dst) {
    int n = blockIdx.x * 8 + (threadIdx.x >> 5);
    if (n >= N_NODES) return;
    int lane = threadIdx.x & 31;
    const __nv_bfloat162* grow = (const __nv_bfloat162*)(g_g2b + (size_t)n * OUT_C);
    float s = 0.f, d = 0.f;
    float2 gv = __bfloat1622float2(grow[lane]);
    s += gv.x * a_src[2*lane] + gv.y * a_src[2*lane + 1];
    d += gv.x * a_dst[2*lane] + gv.y * a_dst[2*lane + 1];
#pragma unroll
    for (int off = 16; off > 0; off >>= 1) {
        s += __shfl_xor_sync(0xffffffffu, s, off);
        d += __shfl_xor_sync(0xffffffffu, d, off);
    }
    if (lane == 0) { g_as2[n] = s; g_ad2[n] = d; }
}

// ---------------- layer-2 fused softmax + aggregation + bias + log_softmax ----------------
__global__ __launch_bounds__(64)
void k_agg2f(const float* __restrict__ b2, float* __restrict__ out) {
    __shared__ int   sh_src[64];
    __shared__ float sh_e[64];
    __shared__ float sh_z;
    __shared__ float red[2];
    int n = blockIdx.x;
    int t = threadIdx.x;
    int lane = t & 31, wrp = t >> 5;
    if (t == 0) sh_z = 0.f;
    int beg = g_rowptr[n], end = g_rowptr[n + 1];
    float acc = 0.f;
    float adv = g_ad2[n];

    for (int c0 = beg; c0 < end; c0 += 64) {
        int cnt = min(64, end - c0);
        __syncthreads();
        if (t < cnt) sh_src[t] = g_csrsrc[c0 + t];
        __syncthreads();
        {
            float e = 0.f;
            if (t < cnt) {
                float l = g_as2[sh_src[t]] + adv;
                l = (l > 0.f) ? l : NEG * l;
                e = __expf(l);
                sh_e[t] = e;
            }
            float ez = e;
#pragma unroll
            for (int off = 16; off > 0; off >>= 1) ez += __shfl_xor_sync(0xffffffffu, ez, off);
            if (lane == 0) atomicAdd(&sh_z, ez);
        }
        __syncthreads();
        int j = 0;
        for (; j + 4 <= cnt; j += 4) {
            int s0 = sh_src[j], s1 = sh_src[j+1], s2 = sh_src[j+2], s3 = sh_src[j+3];
            float e0 = sh_e[j], e1 = sh_e[j+1], e2 = sh_e[j+2], e3 = sh_e[j+3];
            acc += e0 * __bfloat162float(g_g2b[(size_t)s0 * OUT_C + t]);
            acc += e1 * __bfloat162float(g_g2b[(size_t)s1 * OUT_C + t]);
            acc += e2 * __bfloat162float(g_g2b[(size_t)s2 * OUT_C + t]);
            acc += e3 * __bfloat162float(g_g2b[(size_t)s3 * OUT_C + t]);
        }
        for (; j < cnt; j++)
            acc += sh_e[j] * __bfloat162float(g_g2b[(size_t)sh_src[j] * OUT_C + t]);
    }
    __syncthreads();
    float v = acc / sh_z + b2[t];
    float m = v;
#pragma unroll
    for (int off = 16; off > 0; off >>= 1) m = fmaxf(m, __shfl_xor_sync(0xffffffffu, m, off));
    if (lane == 0) red[wrp] = m;
    __syncthreads();
    m = fmaxf(red[0], red[1]);
    float s = expf(v - m);
#pragma unroll
    for (int off = 16; off > 0; off >>= 1) s += __shfl_xor_sync(0xffffffffu, s, off);
    __syncthreads();
    if (lane == 0) red[wrp] = s;
    __syncthreads();
    s = red[0] + red[1];
    out[(size_t)n * OUT_C + t] = v - m - logf(s);
}

// ---------------- launch ----------------
extern "C" void kernel_launch(void* const* d_in, const int* in_sizes, int n_in,
                              void* d_out, int out_size) {
    const float* x     = (const float*)d_in[0];
    const int*   ei    = (const int*)  d_in[1];
    const float* W1    = (const float*)d_in[2];
    const float* asrc1 = (const float*)d_in[3];
    const float* adst1 = (const float*)d_in[4];
    const float* b1    = (const float*)d_in[5];
    const float* W2    = (const float*)d_in[6];
    const float* asrc2 = (const float*)d_in[7];
    const float* adst2 = (const float*)d_in[8];
    const float* b2    = (const float*)d_in[9];
    float* out = (float*)d_out;

    void *p_h1f8, *p_h2b, *p_asd, *p_g2b, *p_xb, *p_w1t, *p_w2t, *p_wab;
    cudaGetSymbolAddress(&p_h1f8, g_h1f8);
    cudaGetSymbolAddress(&p_h2b,  g_h2b);
    cudaGetSymbolAddress(&p_asd,  g_asd);
    cudaGetSymbolAddress(&p_g2b,  g_g2b);
    cudaGetSymbolAddress(&p_xb,   g_xb);
    cudaGetSymbolAddress(&p_w1t,  g_W1t);
    cudaGetSymbolAddress(&p_w2t,  g_W2t);
    cudaGetSymbolAddress(&p_wab,  g_Wab);

    const int SM128 = 2 * (128 + 128) * GPITCH;   // 57344
    const int SM64  = 2 * (128 + 64) * GPITCH;    // 43008
    cudaFuncSetAttribute(gemm_mma<128,2>, cudaFuncAttributeMaxDynamicSharedMemorySize, SM128);
    cudaFuncSetAttribute(gemm_mma<64,0>,  cudaFuncAttributeMaxDynamicSharedMemorySize, SM64);
    cudaFuncSetAttribute(gemm_mma<64,1>,  cudaFuncAttributeMaxDynamicSharedMemorySize, SM64);

    const int TPB = 256;
    const int NB_SCAN = (N_NODES + 1023) / 1024;  // 49
    // CSR build (dst-sorted)
    k_zero_deg<<<(N_NODES + TPB - 1) / TPB, TPB>>>();
    k_count  <<<(E_TOT   + TPB - 1) / TPB, TPB>>>(ei);
    k_scan1  <<<NB_SCAN, 1024>>>();
    k_scan2  <<<1, 32>>>(NB_SCAN);
    k_scan3  <<<NB_SCAN, 1024>>>();
    k_cursor <<<(N_NODES + TPB - 1) / TPB, TPB>>>();
    k_scatter<<<(E_TOT   + TPB - 1) / TPB, TPB>>>(ei);

    // operand prep (bf16)
    k_split_x<<<(int)(((size_t)N_NODES * IN_C + TPB - 1) / TPB), TPB>>>(x);
    k_split_wt<<<(int)(((size_t)IN_C * F1 + TPB - 1) / TPB), TPB>>>(
        W1, (__nv_bfloat16*)p_w1t, IN_C, F1);
    k_split_wt<<<(int)(((size_t)F1 * OUT_C + TPB - 1) / TPB), TPB>>>(
        W2, (__nv_bfloat16*)p_w2t, F1, OUT_C);
    k_w1a<<<64, 512>>>(asrc1, adst1);

    // layer 1
    gemm_mma<128,2><<<dim3(F1 / 128, (N_NODES + 127) / 128), 256, SM128>>>(
        (const __nv_bfloat16*)p_xb, (const __nv_bfloat16*)p_w1t,
        p_h1f8, N_NODES, F1, IN_C);                       // fp8 h1 (bytes/row = F1)
    gemm_mma<64,0><<<dim3(1, (N_NODES + 127) / 128), 256, SM64>>>(
        (const __nv_bfloat16*)p_xb, (const __nv_bfloat16*)p_wab,
        p_asd, N_NODES, 64, IN_C);                        // attn dots
    k_agg1f<<<N_NODES, 512>>>(b1);

    // layer 2
    gemm_mma<64,1><<<dim3(OUT_C / 64, (N_NODES + 127) / 128), 256, SM64>>>(
        (const __nv_bfloat16*)p_h2b, (const __nv_bfloat16*)p_w2t,
        p_g2b, N_NODES, OUT_C, F1);                       // bf16 g2
    k_attn2<<<(N_NODES + 7) / 8, 256>>>(asrc2, adst2);
    k_agg2f<<<N_NODES, 64>>>(b2, out);
}

// round 8
// speedup vs baseline: 4.0392x; 1.1948x over previous
#include <cuda_runtime.h>
#include <cuda_bf16.h>
#include <cuda_fp16.h>
#include <math.h>
#include <stdint.h>

#define N_NODES 50000
#define E_EDGES 1600000
#define E_TOT   (E_EDGES + N_NODES)
#define HEADS   8
#define HID     128
#define IN_C    512
#define F1      (HEADS*HID)   /* 1024 */
#define OUT_C   64
#define NEG     0.2f
#define H1SCALE 64.0f

// ---------------- scratch (device globals: allocation-free) ----------------
__device__ unsigned short g_h1f8[(size_t)N_NODES * (F1/2)];  // e4m3x2 pairs, scale 64
__device__ __nv_bfloat162 g_h2b[(size_t)N_NODES * (F1/2)];   // elu(agg1+b1) bf16 pairs
__device__ float g_asd[(size_t)N_NODES * 64];  // [n][0..7]=as1, [8..15]=ad1
__device__ __nv_bfloat16 g_g2b[(size_t)N_NODES * OUT_C];
__device__ float g_as2[N_NODES];
__device__ float g_ad2[N_NODES];
__device__ int   g_deg[N_NODES];
__device__ int   g_rowptr[N_NODES + 1];
__device__ int   g_cursor[N_NODES];
__device__ int   g_csrsrc[E_TOT];
__device__ int   g_bsum[64];
__device__ int   g_boff[64];

// bf16 operands for tensor-core GEMMs
__device__ __nv_bfloat16 g_xb[(size_t)N_NODES * IN_C];
__device__ __nv_bfloat16 g_W1t[(size_t)F1 * IN_C];    // [n][k] K-major transposed
__device__ __nv_bfloat16 g_W2t[(size_t)OUT_C * F1];
__device__ __nv_bfloat16 g_Wab[(size_t)64 * IN_C];    // attn projection [64][512]

// ---------------- helpers ----------------
__device__ __forceinline__ uint32_t smem_u32(const void* p) {
    uint32_t a;
    asm("{ .reg .u64 t; cvta.to.shared.u64 t, %1; cvt.u32.u64 %0, t; }" : "=r"(a) : "l"(p));
    return a;
}
#define CP16(sa, ga) \
    asm volatile("cp.async.cg.shared.global [%0], [%1], 16;" :: "r"(sa), "l"(ga))
#define CP_COMMIT() asm volatile("cp.async.commit_group;" ::: "memory")
#define CP_WAIT1()  asm volatile("cp.async.wait_group 1;" ::: "memory")
#define CP_WAIT0()  asm volatile("cp.async.wait_group 0;" ::: "memory")

#define MMA16816(c, a, b)                                                      \
    asm volatile("mma.sync.aligned.m16n8k16.row.col.f32.bf16.bf16.f32 "        \
                 "{%0,%1,%2,%3}, {%4,%5,%6,%7}, {%8,%9}, {%0,%1,%2,%3};"       \
                 : "+f"((c)[0]), "+f"((c)[1]), "+f"((c)[2]), "+f"((c)[3])      \
                 : "r"((a)[0]), "r"((a)[1]), "r"((a)[2]), "r"((a)[3]),         \
                   "r"((b)[0]), "r"((b)[1]))

#define LDSM4(d0, d1, d2, d3, addr)                                            \
    asm volatile("ldmatrix.sync.aligned.m8n8.x4.shared.b16 {%0,%1,%2,%3}, [%4];" \
                 : "=r"(d0), "=r"(d1), "=r"(d2), "=r"(d3) : "r"(addr))

__device__ __forceinline__ unsigned short pack_e4m3x2(float lo, float hi) {
    unsigned short r;
    asm("cvt.rn.satfinite.e4m3x2.f32 %0, %1, %2;" : "=h"(r) : "f"(hi), "f"(lo));
    return r;
}
__device__ __forceinline__ float2 unpack_e4m3x2(unsigned short u) {
    uint32_t h2;
    asm("cvt.rn.f16x2.e4m3x2 %0, %1;" : "=r"(h2) : "h"(u));
    __half2 hh = *reinterpret_cast<__half2*>(&h2);
    return __half22float2(hh);
}

// ---------------- CSR build ----------------
__global__ void k_count(const int* __restrict__ ei) {
    int e = blockIdx.x * 256 + threadIdx.x;
    if (e >= E_TOT) return;
    int dst = (e < E_EDGES) ? ei[E_EDGES + e] : (e - E_EDGES);
    atomicAdd(&g_deg[dst], 1);
}
__global__ void k_scan1() {
    __shared__ int sh[1024];
    int t = threadIdx.x, b = blockIdx.x;
    int i = b * 1024 + t;
    int v = (i < N_NODES) ? g_deg[i] : 0;
    sh[t] = v;
    __syncthreads();
    for (int off = 1; off < 1024; off <<= 1) {
        int u = (t >= off) ? sh[t - off] : 0;
        __syncthreads();
        sh[t] += u;
        __syncthreads();
    }
    if (i < N_NODES) g_rowptr[i + 1] = sh[t];
    if (t == 1023) g_bsum[b] = sh[1023];
}
__global__ void k_scan2(int nb) {   // 64 threads, shared scan
    __shared__ int sh[64];
    int t = threadIdx.x;
    int v = (t < nb) ? g_bsum[t] : 0;
    sh[t] = v;
    __syncthreads();
    for (int off = 1; off < 64; off <<= 1) {
        int u = (t >= off) ? sh[t - off] : 0;
        __syncthreads();
        sh[t] += u;
        __syncthreads();
    }
    if (t < nb) g_boff[t] = sh[t] - v;   // exclusive
}
__global__ void k_scan3() {             // add block offsets + init cursor
    int t = threadIdx.x, b = blockIdx.x;
    int i = b * 1024 + t;
    if (i < N_NODES) {
        int v = g_rowptr[i + 1] + g_boff[b];
        g_rowptr[i + 1] = v;
        if (i + 1 < N_NODES) g_cursor[i + 1] = v;
    }
    if (i == 0) { g_rowptr[0] = 0; g_cursor[0] = 0; }
}
__global__ void k_scatter(const int* __restrict__ ei) {
    int e = blockIdx.x * 256 + threadIdx.x;
    if (e >= E_TOT) return;
    int src, dst;
    if (e < E_EDGES) { src = ei[e]; dst = ei[E_EDGES + e]; }
    else             { src = e - E_EDGES; dst = src; }
    int pos = atomicAdd(&g_cursor[dst], 1);
    g_csrsrc[pos] = src;
}

// ---------------- bf16 conversion of x ----------------
__global__ void k_split_x(const float* __restrict__ x) {
    size_t i = (size_t)blockIdx.x * 256 + threadIdx.x;
    if (i >= (size_t)N_NODES * IN_C) return;
    g_xb[i] = __float2bfloat16(x[i]);
}
// transpose W: W[K][N] -> T[n][k] bf16
__global__ void k_split_wt(const float* __restrict__ W, __nv_bfloat16* __restrict__ T,
                           int K, int N) {
    size_t i = (size_t)blockIdx.x * 256 + threadIdx.x;
    if (i >= (size_t)K * N) return;
    int n = (int)(i / K), k = (int)(i % K);
    T[i] = __float2bfloat16(W[(size_t)k * N + n]);
}
// attn projection: Wab[j][k] = sum_c W1t[(head*128+c)*512 + k] * a[head][c]
__global__ void k_w1a(const float* __restrict__ a_src, const float* __restrict__ a_dst) {
    int j = blockIdx.x;             // 0..63
    int k = threadIdx.x;            // 0..511
    float acc = 0.f;
    if (j < 16) {
        int head = j & 7;
        const float* a = (j < 8) ? (a_src + head * HID) : (a_dst + head * HID);
        const __nv_bfloat16* wt = g_W1t + (size_t)(head * HID) * IN_C + k;
        for (int c = 0; c < HID; c++)
            acc += __bfloat162float(wt[(size_t)c * IN_C]) * a[c];
    }
    g_Wab[(size_t)j * IN_C + k] = __float2bfloat16(acc);
}

// ---------------- warp-MMA bf16 GEMM (ldmatrix fragments) ----------------
// C[M,Ntot] = A[M,K] @ B^T, B stored K-major [Ntot][K].
// CTA tile 128xBN, BK=32, 8 warps (4x2), warp tile 32x(BN/2).
// MODE: 0 = fp32 out, 1 = bf16x2 out, 2 = e4m3 out (x H1SCALE, SMEM-staged)
#define GPITCH 112
#define GABYTES (128 * GPITCH)

template <int BN, int MODE>
__global__ __launch_bounds__(256, 2)
void gemm_mma(const __nv_bfloat16* __restrict__ A, const __nv_bfloat16* __restrict__ B,
              void* __restrict__ Cout, int M, int Ntot, int K) {
    constexpr int NF = BN / 16;                 // n-frags per warp
    constexpr int BBYTES = BN * GPITCH;
    constexpr int STG = GABYTES + BBYTES;
    extern __shared__ __align__(16) char smraw[];
    uint32_t sbase = smem_u32(smraw);

    int tid = threadIdx.x;
    int lane = tid & 31, wid = tid >> 5;
    int wm = wid >> 1, wn = wid & 1;
    int m0 = blockIdx.y * 128;
    int n0 = blockIdx.x * BN;
    int KT = K >> 5;

    // ldmatrix lane-address components
    int lrow = (lane & 7) + ((lane >> 3) & 1) * 8;   // 0..15
    int lkoff = ((lane >> 4) & 1) * 16;              // lanes 16-31: +16B (k+8)
    int brow = lane & 15;
    int bkoff = (lane >> 4) * 16;

    auto load_tile = [&](int kt, int s) {
        int k0 = kt << 5;
        uint32_t st = sbase + s * STG;
#pragma unroll
        for (int i = 0; i < 2; i++) {           // A: 512 chunks
            int c = tid + i * 256;
            int r = c >> 2, cg = c & 3;
            int gr = m0 + r; if (gr >= M) gr = M - 1;
            const char* ga = (const char*)(A + (size_t)gr * K + k0) + cg * 16;
            CP16(st + r * GPITCH + cg * 16, ga);
        }
        for (int c = tid; c < BN * 4; c += 256) { // B: BN*4 chunks
            int r = c >> 2, cg = c & 3;
            const char* gb = (const char*)(B + (size_t)(n0 + r) * K + k0) + cg * 16;
            CP16(st + GABYTES + r * GPITCH + cg * 16, gb);
        }
    };

    float acc[2][NF][4];
#pragma unroll
    for (int i = 0; i < 2; i++)
#pragma unroll
        for (int j = 0; j < NF; j++)
#pragma unroll
            for (int q = 0; q < 4; q++) acc[i][j][q] = 0.f;

    load_tile(0, 0);
    CP_COMMIT();

    for (int kt = 0; kt < KT; kt++) {
        int cur = kt & 1;
        if (kt + 1 < KT) { load_tile(kt + 1, cur ^ 1); CP_COMMIT(); CP_WAIT1(); }
        else             { CP_WAIT0(); }
        __syncthreads();

        uint32_t stu = sbase + cur * STG;
#pragma unroll
        for (int ks = 0; ks < 2; ks++) {
            int kb = ks * 32;
            uint32_t ah[2][4];
#pragma unroll
            for (int mf = 0; mf < 2; mf++) {
                uint32_t addr = stu + (uint32_t)((wm * 32 + mf * 16 + lrow) * GPITCH
                               + kb + lkoff);
                LDSM4(ah[mf][0], ah[mf][1], ah[mf][2], ah[mf][3], addr);
            }
            uint32_t bh[NF][2];
#pragma unroll
            for (int nfp = 0; nfp < NF / 2; nfp++) {
                uint32_t addr = stu + GABYTES
                              + (uint32_t)((wn * (BN/2) + nfp * 16 + brow) * GPITCH
                              + kb + bkoff);
                LDSM4(bh[2*nfp][0], bh[2*nfp+1][0], bh[2*nfp][1], bh[2*nfp+1][1], addr);
            }
#pragma unroll
            for (int mf = 0; mf < 2; mf++)
#pragma unroll
                for (int nf = 0; nf < NF; nf++)
                    MMA16816(acc[mf][nf], ah[mf], bh[nf]);
        }
        __syncthreads();
    }

    // ---- epilogue ----
    if (MODE == 2) {
#pragma unroll
        for (int mf = 0; mf < 2; mf++) {
            int rl = wm * 32 + mf * 16 + (lane >> 2);
#pragma unroll
            for (int nf = 0; nf < NF; nf++) {
                int col = wn * (BN/2) + nf * 8 + (lane & 3) * 2;
                *(unsigned short*)(smraw + (size_t)rl * BN + col) =
                    pack_e4m3x2(acc[mf][nf][0] * H1SCALE, acc[mf][nf][1] * H1SCALE);
                *(unsigned short*)(smraw + (size_t)(rl + 8) * BN + col) =
                    pack_e4m3x2(acc[mf][nf][2] * H1SCALE, acc[mf][nf][3] * H1SCALE);
            }
        }
        __syncthreads();
        char* C8 = (char*)Cout;
        constexpr int CHUNKS = 128 * BN / 16;
        for (int c = tid; c < CHUNKS; c += 256) {
            int r = c / (BN / 16), g = c % (BN / 16);
            int gr = m0 + r;
            if (gr < M)
                *(uint4*)(C8 + (size_t)gr * Ntot + n0 + g * 16) =
                    *(const uint4*)(smraw + (size_t)r * BN + g * 16);
        }
    } else {
#pragma unroll
        for (int mf = 0; mf < 2; mf++) {
            int r0 = m0 + wm * 32 + mf * 16 + (lane >> 2);
#pragma unroll
            for (int nf = 0; nf < NF; nf++) {
                int col = n0 + wn * (BN/2) + nf * 8 + (lane & 3) * 2;
                if (MODE == 1) {
                    __nv_bfloat162* Cb = (__nv_bfloat162*)Cout;
                    if (r0 < M)
                        Cb[((size_t)r0 * Ntot + col) >> 1] =
                            __floats2bfloat162_rn(acc[mf][nf][0], acc[mf][nf][1]);
                    if (r0 + 8 < M)
                        Cb[((size_t)(r0 + 8) * Ntot + col) >> 1] =
                            __floats2bfloat162_rn(acc[mf][nf][2], acc[mf][nf][3]);
                } else {
                    float* Cf = (float*)Cout;
                    if (r0 < M)
                        *(float2*)(Cf + (size_t)r0 * Ntot + col) =
                            make_float2(acc[mf][nf][0], acc[mf][nf][1]);
                    if (r0 + 8 < M)
                        *(float2*)(Cf + (size_t)(r0 + 8) * Ntot + col) =
                            make_float2(acc[mf][nf][2], acc[mf][nf][3]);
                }
            }
        }
    }
}

// ---------------- layer-1 fused edge-softmax + aggregation + bias + ELU ----------------
// Block = 256 threads, one dst node per block. Thread t owns channels 4t..4t+3; head = t>>5.
__global__ __launch_bounds__(256)
void k_agg1f(const float* __restrict__ b1) {
    __shared__ int   sh_src[32];
    __shared__ float sh_e[32 * 8];
    __shared__ float sh_z[8];
    int n = blockIdx.x;
    int t = threadIdx.x;
    int lane = t & 31;
    int ht = t >> 5;                 // head of channels 4t..4t+3
    if (t < 8) sh_z[t] = 0.f;
    int beg = g_rowptr[n], end = g_rowptr[n + 1];
    float4 acc = make_float4(0.f, 0.f, 0.f, 0.f);
    const uint32_t* h1u = (const uint32_t*)g_h1f8;   // 256 uint32 per node row

    for (int c0 = beg; c0 < end; c0 += 32) {
        int cnt = min(32, end - c0);
        __syncthreads();
        if (t < cnt) sh_src[t] = g_csrsrc[c0 + t];
        __syncthreads();
        {   // e for cnt edges x 8 heads (threads t = j*8+h, t < cnt*8 <= 256)
            float e = 0.f;
            int h = t & 7;
            if (t < cnt * 8) {
                int j = t >> 3;
                int s = sh_src[j];
                float l = g_asd[(size_t)s * 64 + h] + g_asd[(size_t)n * 64 + 8 + h];
                l = (l > 0.f) ? l : NEG * l;
                e = __expf(l);
                sh_e[t] = e;
            }
            float ez = e;
            ez += __shfl_xor_sync(0xffffffffu, ez, 8);
            ez += __shfl_xor_sync(0xffffffffu, ez, 16);
            if ((lane >> 3) == 0) atomicAdd(&sh_z[h], ez);
        }
        __syncthreads();
        int j = 0;
        for (; j + 4 <= cnt; j += 4) {
            int s0 = sh_src[j], s1 = sh_src[j+1], s2 = sh_src[j+2], s3 = sh_src[j+3];
            float e0 = sh_e[j*8 + ht],      e1 = sh_e[j*8 + 8 + ht];
            float e2 = sh_e[j*8 + 16 + ht], e3 = sh_e[j*8 + 24 + ht];
            uint32_t u0 = h1u[(size_t)s0 * 256 + t];
            uint32_t u1 = h1u[(size_t)s1 * 256 + t];
            uint32_t u2 = h1u[(size_t)s2 * 256 + t];
            uint32_t u3 = h1u[(size_t)s3 * 256 + t];
            float2 a0 = unpack_e4m3x2((unsigned short)(u0 & 0xffff));
            float2 b0 = unpack_e4m3x2((unsigned short)(u0 >> 16));
            float2 a1 = unpack_e4m3x2((unsigned short)(u1 & 0xffff));
            float2 b1v = unpack_e4m3x2((unsigned short)(u1 >> 16));
            float2 a2 = unpack_e4m3x2((unsigned short)(u2 & 0xffff));
            float2 b2v = unpack_e4m3x2((unsigned short)(u2 >> 16));
            float2 a3 = unpack_e4m3x2((unsigned short)(u3 & 0xffff));
            float2 b3v = unpack_e4m3x2((unsigned short)(u3 >> 16));
            acc.x += e0 * a0.x + e1 * a1.x + e2 * a2.x + e3 * a3.x;
            acc.y += e0 * a0.y + e1 * a1.y + e2 * a2.y + e3 * a3.y;
            acc.z += e0 * b0.x + e1 * b1v.x + e2 * b2v.x + e3 * b3v.x;
            acc.w += e0 * b0.y + e1 * b1v.y + e2 * b2v.y + e3 * b3v.y;
        }
        for (; j < cnt; j++) {
            float e = sh_e[j*8 + ht];
            uint32_t u = h1u[(size_t)sh_src[j] * 256 + t];
            float2 a = unpack_e4m3x2((unsigned short)(u & 0xffff));
            float2 b = unpack_e4m3x2((unsigned short)(u >> 16));
            acc.x += e * a.x; acc.y += e * a.y;
            acc.z += e * b.x; acc.w += e * b.y;
        }
    }
    __syncthreads();
    float inv = 1.f / (sh_z[ht] * H1SCALE);
    float4 bb = *(const float4*)(b1 + 4 * t);
    float v0 = acc.x * inv + bb.x;
    float v1 = acc.y * inv + bb.y;
    float v2 = acc.z * inv + bb.z;
    float v3 = acc.w * inv + bb.w;
    v0 = (v0 > 0.f) ? v0 : (expf(v0) - 1.f);
    v1 = (v1 > 0.f) ? v1 : (expf(v1) - 1.f);
    v2 = (v2 > 0.f) ? v2 : (expf(v2) - 1.f);
    v3 = (v3 > 0.f) ? v3 : (expf(v3) - 1.f);
    __nv_bfloat162 p0 = __floats2bfloat162_rn(v0, v1);
    __nv_bfloat162 p1 = __floats2bfloat162_rn(v2, v3);
    uint2 w;
    w.x = *reinterpret_cast<uint32_t*>(&p0);
    w.y = *reinterpret_cast<uint32_t*>(&p1);
    ((uint2*)g_h2b)[(size_t)n * 256 + t] = w;
}

// ---------------- layer-2 attention dots (bf16 g2) ----------------
__global__ void k_attn2(const float* __restrict__ a_src, const float* __restrict__ a_dst) {
    int n = blockIdx.x * 8 + (threadIdx.x >> 5);
    if (n >= N_NODES) return;
    int lane = threadIdx.x & 31;
    const __nv_bfloat162* grow = (const __nv_bfloat162*)(g_g2b + (size_t)n * OUT_C);
    float s = 0.f, d = 0.f;
    float2 gv = __bfloat1622float2(grow[lane]);
    s += gv.x * a_src[2*lane] + gv.y * a_src[2*lane + 1];
    d += gv.x * a_dst[2*lane] + gv.y * a_dst[2*lane + 1];
#pragma unroll
    for (int off = 16; off > 0; off >>= 1) {
        s += __shfl_xor_sync(0xffffffffu, s, off);
        d += __shfl_xor_sync(0xffffffffu, d, off);
    }
    if (lane == 0) { g_as2[n] = s; g_ad2[n] = d; }
}

// ---------------- layer-2 fused softmax + aggregation + bias + log_softmax ----------------
__global__ __launch_bounds__(64)
void k_agg2f(const float* __restrict__ b2, float* __restrict__ out) {
    __shared__ int   sh_src[64];
    __shared__ float sh_e[64];
    __shared__ float sh_z;
    __shared__ float red[2];
    int n = blockIdx.x;
    int t = threadIdx.x;
    int lane = t & 31, wrp = t >> 5;
    if (t == 0) sh_z = 0.f;
    int beg = g_rowptr[n], end = g_rowptr[n + 1];
    float acc = 0.f;
    float adv = g_ad2[n];

    for (int c0 = beg; c0 < end; c0 += 64) {
        int cnt = min(64, end - c0);
        __syncthreads();
        if (t < cnt) sh_src[t] = g_csrsrc[c0 + t];
        __syncthreads();
        {
            float e = 0.f;
            if (t < cnt) {
                float l = g_as2[sh_src[t]] + adv;
                l = (l > 0.f) ? l : NEG * l;
                e = __expf(l);
                sh_e[t] = e;
            }
            float ez = e;
#pragma unroll
            for (int off = 16; off > 0; off >>= 1) ez += __shfl_xor_sync(0xffffffffu, ez, off);
            if (lane == 0) atomicAdd(&sh_z, ez);
        }
        __syncthreads();
        int j = 0;
        for (; j + 4 <= cnt; j += 4) {
            int s0 = sh_src[j], s1 = sh_src[j+1], s2 = sh_src[j+2], s3 = sh_src[j+3];
            float e0 = sh_e[j], e1 = sh_e[j+1], e2 = sh_e[j+2], e3 = sh_e[j+3];
            acc += e0 * __bfloat162float(g_g2b[(size_t)s0 * OUT_C + t]);
            acc += e1 * __bfloat162float(g_g2b[(size_t)s1 * OUT_C + t]);
            acc += e2 * __bfloat162float(g_g2b[(size_t)s2 * OUT_C + t]);
            acc += e3 * __bfloat162float(g_g2b[(size_t)s3 * OUT_C + t]);
        }
        for (; j < cnt; j++)
            acc += sh_e[j] * __bfloat162float(g_g2b[(size_t)sh_src[j] * OUT_C + t]);
    }
    __syncthreads();
    float v = acc / sh_z + b2[t];
    float m = v;
#pragma unroll
    for (int off = 16; off > 0; off >>= 1) m = fmaxf(m, __shfl_xor_sync(0xffffffffu, m, off));
    if (lane == 0) red[wrp] = m;
    __syncthreads();
    m = fmaxf(red[0], red[1]);
    float s = expf(v - m);
#pragma unroll
    for (int off = 16; off > 0; off >>= 1) s += __shfl_xor_sync(0xffffffffu, s, off);
    __syncthreads();
    if (lane == 0) red[wrp] = s;
    __syncthreads();
    s = red[0] + red[1];
    out[(size_t)n * OUT_C + t] = v - m - logf(s);
}

// ---------------- launch ----------------
extern "C" void kernel_launch(void* const* d_in, const int* in_sizes, int n_in,
                              void* d_out, int out_size) {
    const float* x     = (const float*)d_in[0];
    const int*   ei    = (const int*)  d_in[1];
    const float* W1    = (const float*)d_in[2];
    const float* asrc1 = (const float*)d_in[3];
    const float* adst1 = (const float*)d_in[4];
    const float* b1    = (const float*)d_in[5];
    const float* W2    = (const float*)d_in[6];
    const float* asrc2 = (const float*)d_in[7];
    const float* adst2 = (const float*)d_in[8];
    const float* b2    = (const float*)d_in[9];
    float* out = (float*)d_out;

    void *p_h1f8, *p_h2b, *p_asd, *p_g2b, *p_xb, *p_w1t, *p_w2t, *p_wab, *p_deg;
    cudaGetSymbolAddress(&p_h1f8, g_h1f8);
    cudaGetSymbolAddress(&p_h2b,  g_h2b);
    cudaGetSymbolAddress(&p_asd,  g_asd);
    cudaGetSymbolAddress(&p_g2b,  g_g2b);
    cudaGetSymbolAddress(&p_xb,   g_xb);
    cudaGetSymbolAddress(&p_w1t,  g_W1t);
    cudaGetSymbolAddress(&p_w2t,  g_W2t);
    cudaGetSymbolAddress(&p_wab,  g_Wab);
    cudaGetSymbolAddress(&p_deg,  g_deg);

    const int SM128 = 2 * (128 + 128) * GPITCH;   // 57344
    const int SM64  = 2 * (128 + 64) * GPITCH;    // 43008
    cudaFuncSetAttribute(gemm_mma<128,2>, cudaFuncAttributeMaxDynamicSharedMemorySize, SM128);
    cudaFuncSetAttribute(gemm_mma<64,0>,  cudaFuncAttributeMaxDynamicSharedMemorySize, SM64);
    cudaFuncSetAttribute(gemm_mma<64,1>,  cudaFuncAttributeMaxDynamicSharedMemorySize, SM64);

    const int TPB = 256;
    const int NB_SCAN = (N_NODES + 1023) / 1024;  // 49
    // CSR build (dst-sorted)
    cudaMemsetAsync(p_deg, 0, N_NODES * sizeof(int));
    k_count  <<<(E_TOT   + TPB - 1) / TPB, TPB>>>(ei);
    k_scan1  <<<NB_SCAN, 1024>>>();
    k_scan2  <<<1, 64>>>(NB_SCAN);
    k_scan3  <<<NB_SCAN, 1024>>>();
    k_scatter<<<(E_TOT   + TPB - 1) / TPB, TPB>>>(ei);

    // operand prep (bf16)
    k_split_x<<<(int)(((size_t)N_NODES * IN_C + TPB - 1) / TPB), TPB>>>(x);
    k_split_wt<<<(int)(((size_t)IN_C * F1 + TPB - 1) / TPB), TPB>>>(
        W1, (__nv_bfloat16*)p_w1t, IN_C, F1);
    k_split_wt<<<(int)(((size_t)F1 * OUT_C + TPB - 1) / TPB), TPB>>>(
        W2, (__nv_bfloat16*)p_w2t, F1, OUT_C);
    k_w1a<<<64, 512>>>(asrc1, adst1);

    // layer 1
    gemm_mma<128,2><<<dim3(F1 / 128, (N_NODES + 127) / 128), 256, SM128>>>(
        (const __nv_bfloat16*)p_xb, (const __nv_bfloat16*)p_w1t,
        p_h1f8, N_NODES, F1, IN_C);                       // fp8 h1
    gemm_mma<64,0><<<dim3(1, (N_NODES + 127) / 128), 256, SM64>>>(
        (const __nv_bfloat16*)p_xb, (const __nv_bfloat16*)p_wab,
        p_asd, N_NODES, 64, IN_C);                        // attn dots
    k_agg1f<<<N_NODES, 256>>>(b1);

    // layer 2
    gemm_mma<64,1><<<dim3(OUT_C / 64, (N_NODES + 127) / 128), 256, SM64>>>(
        (const __nv_bfloat16*)p_h2b, (const __nv_bfloat16*)p_w2t,
        p_g2b, N_NODES, OUT_C, F1);                       // bf16 g2
    k_attn2<<<(N_NODES + 7) / 8, 256>>>(asrc2, adst2);
    k_agg2f<<<N_NODES, 64>>>(b2, out);
}